// round 14
// baseline (speedup 1.0000x reference)
#include <cuda_runtime.h>
#include <math.h>
#include <stdint.h>

// Problem constants
#define BB  2
#define LL  4096
#define DD  2048
#define HH  16
#define KK  128
#define VV  128
#define MROWS (BB*LL)          // 8192
#define QSCALE 0.08838834764831845f   // 128^-0.5
#define LNEPS 1e-5f

// recurrence time-split
#define NB  32
#define TB  (LL/NB)            // 128
#define NBH (BB*HH)            // 32

// GEMM tiling: CTA tile 256(M) x 256(N), two M=128 sub-tiles sharing B smem.
#define TBM 256                // CTA M (2 sub-tiles of 128)
#define TBN 256
#define TBK 32

#define TSTAGES 2
#define A_SUB_BYTES   (128*TBK*4)     // 16384 per M sub-tile
#define A_STAGE_BYTES (2*A_SUB_BYTES) // 32768
#define B_STAGE_BYTES (TBN*TBK*4)     // 32768
#define STAGE_BYTES   (A_STAGE_BYTES + B_STAGE_BYTES)   // 65536
#define TC_SMEM       (TSTAGES*STAGE_BYTES + 1024)      // 132096

// fallback (correctness-only) smem: single stage, padded, one sub-tile at a time
#define PADK 36
#define MMA_SMEM ((128 + TBN) * PADK * 4)               // 55296

#define GEMM_SMEM (TC_SMEM > MMA_SMEM ? TC_SMEM : MMA_SMEM)

// tcgen05 idesc (per M=128 sub-tile): dtype=F32|atype=TF32|btype=TF32|(N/8)<<17|(128/16)<<24
#define IDESC_TF32 ((1u<<4) | (2u<<7) | (2u<<10) | ((TBN/8)<<17) | ((128/16)<<24))
#define DESC_BASE_SW128 ( (2ull<<61) | (1ull<<46) | (64ull<<32) | (1ull<<16) )

#if defined(__CUDA_ARCH_FEAT_SM103_ALL) || defined(__CUDA_ARCH_FEAT_SM100_ALL)
#define TC_PATH 1
#else
#define TC_PATH 0
#endif

// -------------------- scratch --------------------
__device__ float g_q [(size_t)MROWS * DD];
__device__ float g_k [(size_t)MROWS * DD];
__device__ float g_v [(size_t)MROWS * DD];
__device__ float g_eg[(size_t)MROWS * DD];
__device__ float g_y [(size_t)MROWS * DD];
__device__ float g_xt[(size_t)MROWS * DD];
__device__ float g_w [5][(size_t)DD * DD];
__device__ float g_sloc  [(size_t)NB * NBH * KK * VV];
__device__ float g_sstart[(size_t)NB * NBH * KK * VV];
__device__ float g_dec   [(size_t)NB * NBH * KK];

__device__ __forceinline__ float* pick_buf(int sel) {
    switch (sel) {
        case 1: return g_q;
        case 2: return g_k;
        case 3: return g_v;
        case 4: return g_eg;
        case 5: return g_y;
        case 6: return g_xt;
        default: return g_w[sel - 7];
    }
}

// -------------------- tf32 rounding pre-pass --------------------
__device__ __forceinline__ float tf32_rna(float f) {
    uint32_t u;
    asm("cvt.rna.tf32.f32 %0, %1;" : "=r"(u) : "f"(f));
    return __uint_as_float(u);
}

__global__ __launch_bounds__(256)
void tf32_round_kernel(const float* __restrict__ in, int outsel, int n)
{
    float* out = pick_buf(outsel);
    int i = (blockIdx.x * 256 + threadIdx.x) * 4;
    if (i < n) {
        float4 v = *(const float4*)(in + i);
        v.x = tf32_rna(v.x); v.y = tf32_rna(v.y);
        v.z = tf32_rna(v.z); v.w = tf32_rna(v.w);
        *(float4*)(out + i) = v;
    }
}

__global__ __launch_bounds__(256)
void tf32_round_w_kernel(const float* __restrict__ w0, const float* __restrict__ w1,
                         const float* __restrict__ w2, const float* __restrict__ w3,
                         const float* __restrict__ w4)
{
    const float* in;
    switch (blockIdx.y) {
        case 0: in = w0; break;
        case 1: in = w1; break;
        case 2: in = w2; break;
        case 3: in = w3; break;
        default: in = w4; break;
    }
    float* out = g_w[blockIdx.y];
    int i = (blockIdx.x * 256 + threadIdx.x) * 4;
    float4 v = *(const float4*)(in + i);
    v.x = tf32_rna(v.x); v.y = tf32_rna(v.y);
    v.z = tf32_rna(v.z); v.w = tf32_rna(v.w);
    *(float4*)(out + i) = v;
}

// -------------------- common helpers --------------------
__device__ __forceinline__ uint32_t smem_u32(const void* p) {
    return (uint32_t)__cvta_generic_to_shared(p);
}
__device__ __forceinline__ void cp16(uint32_t sa, const float* g) {
    asm volatile("cp.async.cg.shared.global [%0], [%1], 16;\n" :: "r"(sa), "l"(g));
}

#if TC_PATH
__device__ __forceinline__ void mbar_init(uint32_t a, uint32_t cnt) {
    asm volatile("mbarrier.init.shared.b64 [%0], %1;" :: "r"(a), "r"(cnt) : "memory");
}
__device__ __forceinline__ void mbar_wait(uint32_t a, uint32_t parity) {
    asm volatile(
        "{\n\t.reg .pred P;\n\t"
        "WLOOP:\n\t"
        "mbarrier.try_wait.parity.shared.b64 P, [%0], %1;\n\t"
        "@P bra.uni WDONE;\n\t"
        "bra.uni WLOOP;\n\t"
        "WDONE:\n\t}"
        :: "r"(a), "r"(parity) : "memory");
}
__device__ __forceinline__ void mma_tf32_tc(uint32_t d, uint64_t ad, uint64_t bd,
                                            uint32_t idesc, uint32_t en) {
    asm volatile(
        "{\n\t.reg .pred p;\n\t"
        "setp.ne.u32 p, %4, 0;\n\t"
        "tcgen05.mma.cta_group::1.kind::tf32 [%0], %1, %2, %3, {%5,%5,%5,%5}, p;\n\t"
        "}"
        :: "r"(d), "l"(ad), "l"(bd), "r"(idesc), "r"(en), "r"(0u) : "memory");
}
__device__ __forceinline__ void tc_commit(uint32_t mbar) {
    asm volatile(
        "tcgen05.commit.cta_group::1.mbarrier::arrive::one.shared::cluster.b64 [%0];"
        :: "r"(mbar) : "memory");
}
#else
__device__ __forceinline__ void mma_tf32(float* c, const uint32_t* a, const uint32_t* b)
{
    asm volatile(
        "mma.sync.aligned.m16n8k8.row.col.f32.tf32.tf32.f32 "
        "{%0,%1,%2,%3},{%4,%5,%6,%7},{%8,%9},{%0,%1,%2,%3};\n"
        : "+f"(c[0]), "+f"(c[1]), "+f"(c[2]), "+f"(c[3])
        : "r"(a[0]), "r"(a[1]), "r"(a[2]), "r"(a[3]), "r"(b[0]), "r"(b[1]));
}
#endif

// -------------------- unified GEMM: C = act(A @ B^T), CTA tile 256x256 --------------------
// grid.x = 8 * nproj (bn index in low 3 bits), grid.y = M/256, 256 threads.
__global__ __launch_bounds__(256, 1)
void gemm_uni(int Asel, int Bsel0, float* __restrict__ Cext, int Csel0, int actPack)
{
    extern __shared__ float dsm[];

    const int bnIdx = blockIdx.x & 7;
    const int proj  = blockIdx.x >> 3;

    const float* A = (const float*)pick_buf(Asel);
    const float* B = (const float*)pick_buf(Bsel0 + proj);
    float*       C = Csel0 ? pick_buf(Csel0 + proj) : Cext;
    const int mode = (actPack >> (4 * proj)) & 15;

    const int bm = blockIdx.y * TBM;
    const int bn = bnIdx * TBN;

    const int tid  = threadIdx.x;
    const int warp = tid >> 5, lane = tid & 31;

#if TC_PATH
    __shared__ __align__(8) unsigned long long s_mbar[TSTAGES + 1];
    __shared__ uint32_t s_tmem[1];

    const uint32_t rawb = smem_u32(dsm);
    const uint32_t smb  = (rawb + 1023u) & ~1023u;

    if (warp == 0) {
        asm volatile(
            "tcgen05.alloc.cta_group::1.sync.aligned.shared::cta.b32 [%0], %1;"
            :: "r"(smem_u32(s_tmem)), "r"(512u) : "memory");
        asm volatile("tcgen05.relinquish_alloc_permit.cta_group::1.sync.aligned;");
    }
    if (tid == 0) {
        #pragma unroll
        for (int i = 0; i < TSTAGES + 1; i++)
            mbar_init(smem_u32(&s_mbar[i]), 1u);
    }
    __syncthreads();
    uint32_t tmem_base;
    asm volatile("ld.shared.b32 %0, [%1];" : "=r"(tmem_base) : "r"(smem_u32(s_tmem)));

    const int lr  = tid >> 3;    // 0..31
    const int seg = tid & 7;     // 16B segment within 128B row

    auto loader = [&](int c) {
        const uint32_t sb = smb + (uint32_t)((c & 1) * STAGE_BYTES);
        // two A sub-tiles (rows bm..bm+127 and bm+128..bm+255)
        const float* Ab = A + (size_t)bm * DD + c * TBK;
        #pragma unroll
        for (int i = 0; i < 8; i++) {
            const int row = lr + 32 * i;   // 0..255
            const uint32_t sw = (uint32_t)row * 128u + (uint32_t)((seg ^ (row & 7)) * 16);
            cp16(sb + sw, Ab + (size_t)row * DD + seg * 4);
        }
        const uint32_t bbB = sb + A_STAGE_BYTES;
        const float* Bb = B + (size_t)bn * DD + c * TBK;
        #pragma unroll
        for (int i = 0; i < 8; i++) {
            const int row = lr + 32 * i;
            const uint32_t sw = (uint32_t)row * 128u + (uint32_t)((seg ^ (row & 7)) * 16);
            cp16(bbB + sw, Bb + (size_t)row * DD + seg * 4);
        }
        asm volatile("cp.async.commit_group;\n");
    };

    loader(0); loader(1);

    const int nk = DD / TBK;   // 64
    for (int c = 0; c < nk; c++) {
        asm volatile("cp.async.wait_group 1;\n");
        __syncthreads();

        if (tid == 0) {
            asm volatile("fence.proxy.async.shared::cta;" ::: "memory");
            const uint32_t sb = smb + (uint32_t)((c & 1) * STAGE_BYTES);
            const uint64_t bd = DESC_BASE_SW128 | (uint64_t)(((sb + A_STAGE_BYTES) >> 4) & 0x3FFF);
            #pragma unroll
            for (int m = 0; m < 2; m++) {
                const uint64_t ad = DESC_BASE_SW128 |
                    (uint64_t)(((sb + m * A_SUB_BYTES) >> 4) & 0x3FFF);
                #pragma unroll
                for (int k = 0; k < 4; k++)
                    mma_tf32_tc(tmem_base + m * 256, ad + 2 * k, bd + 2 * k, IDESC_TF32,
                                (c > 0 || k > 0) ? 1u : 0u);
            }
            tc_commit(smem_u32(&s_mbar[c & 1]));
        }

        if (c + 2 < nk) {
            // stage (c+2)&1 == c&1 holds chunk c whose MMA was just issued
            mbar_wait(smem_u32(&s_mbar[c & 1]), (uint32_t)((c >> 1) & 1));
            loader(c + 2);
        } else {
            asm volatile("cp.async.commit_group;\n");
        }
    }

    if (tid == 0) tc_commit(smem_u32(&s_mbar[TSTAGES]));
    __syncthreads();
    mbar_wait(smem_u32(&s_mbar[TSTAGES]), 0u);
    asm volatile("tcgen05.fence::after_thread_sync;" ::: "memory");

    // epilogue: per sub-tile, warps 0-3 cols [0,128), warps 4-7 cols [128,256)
    const int sub = warp & 3;
    const int cb0 = (warp >> 2) * 128;
    #pragma unroll
    for (int m = 0; m < 2; m++) {
        const int row = bm + m * 128 + sub * 32 + lane;
        #pragma unroll
        for (int cb = 0; cb < 128; cb += 32) {
            uint32_t r[32];
            asm volatile(
                "tcgen05.ld.sync.aligned.32x32b.x32.b32 "
                "{%0,%1,%2,%3,%4,%5,%6,%7,%8,%9,%10,%11,%12,%13,%14,%15,"
                "%16,%17,%18,%19,%20,%21,%22,%23,%24,%25,%26,%27,%28,%29,%30,%31}, [%32];"
                : "=r"(r[0]),"=r"(r[1]),"=r"(r[2]),"=r"(r[3]),"=r"(r[4]),"=r"(r[5]),"=r"(r[6]),"=r"(r[7]),
                  "=r"(r[8]),"=r"(r[9]),"=r"(r[10]),"=r"(r[11]),"=r"(r[12]),"=r"(r[13]),"=r"(r[14]),"=r"(r[15]),
                  "=r"(r[16]),"=r"(r[17]),"=r"(r[18]),"=r"(r[19]),"=r"(r[20]),"=r"(r[21]),"=r"(r[22]),"=r"(r[23]),
                  "=r"(r[24]),"=r"(r[25]),"=r"(r[26]),"=r"(r[27]),"=r"(r[28]),"=r"(r[29]),"=r"(r[30]),"=r"(r[31])
                : "r"(tmem_base + m * 256 + cb0 + cb));
            asm volatile("tcgen05.wait::ld.sync.aligned;" ::: "memory");

            float* Crow = C + (size_t)row * DD + bn + cb0 + cb;
            #pragma unroll
            for (int e = 0; e < 32; e += 4) {
                float o[4];
                #pragma unroll
                for (int t = 0; t < 4; t++) {
                    float vv = __uint_as_float(r[e + t]);
                    if (mode == 1) vv *= QSCALE;
                    else if (mode == 2) vv = 1.0f / (1.0f + __expf(-vv));
                    o[t] = vv;
                }
                *(float4*)(Crow + e) = make_float4(o[0], o[1], o[2], o[3]);
            }
        }
    }

    __syncthreads();
    if (warp == 0) {
        asm volatile("tcgen05.dealloc.cta_group::1.sync.aligned.b32 %0, %1;"
                     :: "r"(tmem_base), "r"(512u));
    }

#else
    // ====== mma.sync fallback (correctness-only; never runs on sm_103a) ======
    const int wm  = (warp >> 2) * 64;
    const int wn  = (warp & 3) * 64;
    const int grp = lane >> 2, t4 = lane & 3;

    const int lrow = tid >> 3;
    const int lk   = (tid & 7) * 4;

    float* Asm = dsm;
    float* Bsm = dsm + 128 * PADK;

    for (int msub = 0; msub < 2; msub++) {
        const int bms = bm + msub * 128;
        float acc[4][8][4];
        #pragma unroll
        for (int i = 0; i < 4; i++)
            #pragma unroll
            for (int j = 0; j < 8; j++)
                #pragma unroll
                for (int e = 0; e < 4; e++) acc[i][j][e] = 0.f;

        for (int kt = 0; kt < DD; kt += TBK) {
            __syncthreads();
            #pragma unroll
            for (int i = 0; i < 4; i++) {
                const int row = lrow + 32 * i;
                const float4 av = *(const float4*)(A + (size_t)(bms + row) * DD + kt + lk);
                *(float4*)&Asm[row * PADK + lk] = av;
            }
            #pragma unroll
            for (int i = 0; i < 8; i++) {
                const int row = lrow + 32 * i;
                const float4 bv = *(const float4*)(B + (size_t)(bn + row) * DD + kt + lk);
                *(float4*)&Bsm[row * PADK + lk] = bv;
            }
            __syncthreads();

            #pragma unroll
            for (int k8 = 0; k8 < TBK; k8 += 8) {
                uint32_t a[4][4], b[8][2];
                #pragma unroll
                for (int i = 0; i < 4; i++) {
                    const float* ap = Asm + (wm + i * 16 + grp) * PADK + k8 + t4;
                    a[i][0] = __float_as_uint(ap[0]);
                    a[i][1] = __float_as_uint(ap[8 * PADK]);
                    a[i][2] = __float_as_uint(ap[4]);
                    a[i][3] = __float_as_uint(ap[8 * PADK + 4]);
                }
                #pragma unroll
                for (int j = 0; j < 8; j++) {
                    const float* bp = Bsm + (wn + j * 8 + grp) * PADK + k8 + t4;
                    b[j][0] = __float_as_uint(bp[0]);
                    b[j][1] = __float_as_uint(bp[4]);
                }
                #pragma unroll
                for (int i = 0; i < 4; i++)
                    #pragma unroll
                    for (int j = 0; j < 8; j++)
                        mma_tf32(acc[i][j], a[i], b[j]);
            }
        }

        #pragma unroll
        for (int i = 0; i < 4; i++) {
            const int r0 = bms + wm + i * 16 + grp;
            #pragma unroll
            for (int j = 0; j < 8; j++) {
                const int c0 = bn + wn + j * 8 + t4 * 2;
                float o[4];
                #pragma unroll
                for (int e = 0; e < 4; e++) {
                    float vv = acc[i][j][e];
                    if (mode == 1) vv *= QSCALE;
                    else if (mode == 2) vv = 1.0f / (1.0f + __expf(-vv));
                    o[e] = vv;
                }
                *(float2*)&C[(size_t)r0 * DD + c0]       = make_float2(o[0], o[1]);
                *(float2*)&C[(size_t)(r0 + 8) * DD + c0] = make_float2(o[2], o[3]);
            }
        }
        __syncthreads();
    }
#endif
}

// ==================== time-split GLA recurrence ====================

// Phase 1 (k-sliced warps, round-13 proven).
__global__ __launch_bounds__(256, 2)
void gla_p1()
{
    const int lane = threadIdx.x & 31;
    const int w    = threadIdx.x >> 5;
    const int kl   = lane & 3;
    const int vl   = lane >> 2;
    const int vc   = blockIdx.x & 1;
    const int blk  = blockIdx.x >> 1;
    const int h    = blockIdx.y;
    const int b    = blockIdx.z;
    const int kofs = w * 16 + kl * 4;
    const int vabs = vc * 64 + vl * 8;

    const size_t base = ((size_t)b * LL + (size_t)blk * TB) * DD + (size_t)h * KK;
    const float* kp = g_k  + base + kofs;
    const float* gp = g_eg + base + kofs;
    const float* vp = g_v  + base + vabs;

    float S[4][8];
    float dp[4];
    #pragma unroll
    for (int i = 0; i < 4; i++) {
        dp[i] = 1.f;
        #pragma unroll
        for (int j = 0; j < 8; j++) S[i][j] = 0.f;
    }

    struct F { float4 k, g, v0, v1; } f[3];
    auto ld = [&](F& fr, int t) {
        const size_t off = (size_t)t * DD;
        fr.k  = *(const float4*)(kp + off);
        fr.g  = *(const float4*)(gp + off);
        fr.v0 = *(const float4*)(vp + off);
        fr.v1 = *(const float4*)(vp + off + 4);
    };
    ld(f[0], 0); ld(f[1], 1);

    #pragma unroll 3
    for (int t = 0; t < TB; ++t) {
        const int tn = (t + 2 < TB) ? (t + 2) : (TB - 1);
        ld(f[(t + 2) % 3], tn);

        const F& c = f[t % 3];
        float k[4] = {c.k.x, c.k.y, c.k.z, c.k.w};
        float g[4] = {c.g.x, c.g.y, c.g.z, c.g.w};
        float v[8] = {c.v0.x, c.v0.y, c.v0.z, c.v0.w, c.v1.x, c.v1.y, c.v1.z, c.v1.w};

        #pragma unroll
        for (int i = 0; i < 4; i++) {
            dp[i] *= g[i];
            #pragma unroll
            for (int j = 0; j < 8; j++)
                S[i][j] = fmaf(S[i][j], g[i], k[i] * v[j]);
        }
    }

    const size_t bh = (size_t)b * HH + h;
    const size_t so = (((size_t)blk * NBH + bh) * KK + kofs) * VV + vabs;
    #pragma unroll
    for (int i = 0; i < 4; i++) {
        *(float4*)&g_sloc[so + (size_t)i * VV]     = make_float4(S[i][0], S[i][1], S[i][2], S[i][3]);
        *(float4*)&g_sloc[so + (size_t)i * VV + 4] = make_float4(S[i][4], S[i][5], S[i][6], S[i][7]);
    }
    if (vl == 0 && vc == 0) {
        const size_t dofs = ((size_t)blk * NBH + bh) * KK + kofs;
        #pragma unroll
        for (int i = 0; i < 4; i++) g_dec[dofs + i] = dp[i];
    }
}

// Phase 2: sequential combine over NB blocks.
__global__ __launch_bounds__(256)
void gla_p2(float* __restrict__ out_state)
{
    const int tid   = threadIdx.x;
    const int kq    = tid & 15;
    const int vslot = tid >> 4;
    const int vabs  = blockIdx.x * 32 + vslot * 2;
    const int h     = blockIdx.y;
    const int b     = blockIdx.z;
    const size_t bh = (size_t)b * HH + h;

    float R0[8], R1[8];
    #pragma unroll
    for (int i = 0; i < 8; i++) { R0[i] = 0.f; R1[i] = 0.f; }

    for (int i = 0; i < NB; i++) {
        const size_t so   = (((size_t)i * NBH + bh) * KK + kq * 8) * VV + vabs;
        const size_t dofs = ((size_t)i * NBH + bh) * KK + kq * 8;
        #pragma unroll
        for (int j = 0; j < 8; j++) {
            *(float2*)&g_sstart[so + (size_t)j * VV] = make_float2(R0[j], R1[j]);
            const float2 sl = *(const float2*)&g_sloc[so + (size_t)j * VV];
            const float  d  = g_dec[dofs + j];
            R0[j] = fmaf(d, R0[j], sl.x);
            R1[j] = fmaf(d, R1[j], sl.y);
        }
    }

    const size_t fsbase = (bh * KK + kq * 8) * VV + vabs;
    #pragma unroll
    for (int j = 0; j < 8; j++)
        *(float2*)&out_state[fsbase + (size_t)j * VV] = make_float2(R0[j], R1[j]);
}

// Phase 3 (Layout D, round-12 proven).
__global__ __launch_bounds__(256, 2)
void gla_p3()
{
    const int lane = threadIdx.x & 31;
    const int w    = threadIdx.x >> 5;
    const int vc   = blockIdx.x & 1;
    const int blk  = blockIdx.x >> 1;
    const int vabs = vc * 64 + w * 8;
    const int h    = blockIdx.y;
    const int b    = blockIdx.z;

    const size_t base = ((size_t)b * LL + (size_t)blk * TB) * DD + (size_t)h * KK;
    const float* qp = g_q  + base + lane * 4;
    const float* kp = g_k  + base + lane * 4;
    const float* gp = g_eg + base + lane * 4;
    const float* vp = g_v  + base + vabs;
    float*       yp = g_y  + base + vabs;

    const size_t bh = (size_t)b * HH + h;
    const size_t so = (((size_t)blk * NBH + bh) * KK + lane * 4) * VV + vabs;

    float S[4][8];
    #pragma unroll
    for (int i = 0; i < 4; i++) {
        const float4 s0 = *(const float4*)&g_sstart[so + (size_t)i * VV];
        const float4 s1 = *(const float4*)&g_sstart[so + (size_t)i * VV + 4];
        S[i][0] = s0.x; S[i][1] = s0.y; S[i][2] = s0.z; S[i][3] = s0.w;
        S[i][4] = s1.x; S[i][5] = s1.y; S[i][6] = s1.z; S[i][7] = s1.w;
    }

    struct F { float4 q, k, g, v0, v1; } f[3];
    auto ld = [&](F& fr, int t) {
        const size_t off = (size_t)t * DD;
        fr.q  = *(const float4*)(qp + off);
        fr.k  = *(const float4*)(kp + off);
        fr.g  = *(const float4*)(gp + off);
        fr.v0 = *(const float4*)(vp + off);
        fr.v1 = *(const float4*)(vp + off + 4);
    };
    ld(f[0], 0); ld(f[1], 1);

    #pragma unroll 3
    for (int t = 0; t < TB; ++t) {
        const int tn = (t + 2 < TB) ? (t + 2) : (TB - 1);
        ld(f[(t + 2) % 3], tn);

        const F& c = f[t % 3];
        float q[4] = {c.q.x, c.q.y, c.q.z, c.q.w};
        float k[4] = {c.k.x, c.k.y, c.k.z, c.k.w};
        float g[4] = {c.g.x, c.g.y, c.g.z, c.g.w};
        float v[8] = {c.v0.x, c.v0.y, c.v0.z, c.v0.w, c.v1.x, c.v1.y, c.v1.z, c.v1.w};

        float acc[8] = {0.f,0.f,0.f,0.f,0.f,0.f,0.f,0.f};
        #pragma unroll
        for (int i = 0; i < 4; i++) {
            #pragma unroll
            for (int j = 0; j < 8; j++) {
                S[i][j] = fmaf(S[i][j], g[i], k[i] * v[j]);
                acc[j]  = fmaf(q[i], S[i][j], acc[j]);
            }
        }

        #pragma unroll
        for (int m = 1; m <= 16; m <<= 1) {
            #pragma unroll
            for (int j = 0; j < 8; j++)
                acc[j] += __shfl_xor_sync(0xffffffffu, acc[j], m);
        }
        if (lane == 0) {
            *(float4*)(yp + (size_t)t * DD)     = make_float4(acc[0], acc[1], acc[2], acc[3]);
            *(float4*)(yp + (size_t)t * DD + 4) = make_float4(acc[4], acc[5], acc[6], acc[7]);
        }
    }
}

// -------------------- LayerNorm --------------------
__global__ __launch_bounds__(256)
void ln_kernel(const float* __restrict__ gamma, const float* __restrict__ beta)
{
    const int row = blockIdx.x;
    const float* yr   = g_y + (size_t)row * DD;
    float*       orow = g_q + (size_t)row * DD;
    const int c0 = threadIdx.x * 8;

    const float4 v0 = *(const float4*)(yr + c0);
    const float4 v1 = *(const float4*)(yr + c0 + 4);
    float vals[8] = {v0.x, v0.y, v0.z, v0.w, v1.x, v1.y, v1.z, v1.w};

    float s = 0.f, s2 = 0.f;
    #pragma unroll
    for (int i = 0; i < 8; i++) { s += vals[i]; s2 = fmaf(vals[i], vals[i], s2); }

    #pragma unroll
    for (int m = 16; m >= 1; m >>= 1) {
        s  += __shfl_xor_sync(0xffffffffu, s,  m);
        s2 += __shfl_xor_sync(0xffffffffu, s2, m);
    }
    __shared__ float ws[8], ws2[8];
    const int warp = threadIdx.x >> 5;
    if ((threadIdx.x & 31) == 0) { ws[warp] = s; ws2[warp] = s2; }
    __syncthreads();
    float ts = 0.f, ts2 = 0.f;
    #pragma unroll
    for (int i = 0; i < 8; i++) { ts += ws[i]; ts2 += ws2[i]; }

    const float mu  = ts * (1.0f / DD);
    const float var = ts2 * (1.0f / DD) - mu * mu;
    const float r   = rsqrtf(var + LNEPS);

    const float4 ga0 = *(const float4*)(gamma + c0);
    const float4 ga1 = *(const float4*)(gamma + c0 + 4);
    const float4 be0 = *(const float4*)(beta + c0);
    const float4 be1 = *(const float4*)(beta + c0 + 4);
    float gm[8] = {ga0.x, ga0.y, ga0.z, ga0.w, ga1.x, ga1.y, ga1.z, ga1.w};
    float bt[8] = {be0.x, be0.y, be0.z, be0.w, be1.x, be1.y, be1.z, be1.w};

    float o[8];
    #pragma unroll
    for (int i = 0; i < 8; i++)
        o[i] = tf32_rna(fmaf((vals[i] - mu) * r, gm[i], bt[i]));
    *(float4*)(orow + c0)     = make_float4(o[0], o[1], o[2], o[3]);
    *(float4*)(orow + c0 + 4) = make_float4(o[4], o[5], o[6], o[7]);
}

// -------------------- launch --------------------
extern "C" void kernel_launch(void* const* d_in, const int* in_sizes, int n_in,
                              void* d_out, int out_size)
{
    const float* x     = (const float*)d_in[0];
    const float* Wq    = (const float*)d_in[1];
    const float* Wk    = (const float*)d_in[2];
    const float* Wv    = (const float*)d_in[3];
    const float* Wg    = (const float*)d_in[4];
    const float* Wo    = (const float*)d_in[5];
    const float* gamma = (const float*)d_in[6];
    const float* beta  = (const float*)d_in[7];
    float* out = (float*)d_out;

    cudaFuncSetAttribute(gemm_uni, cudaFuncAttributeMaxDynamicSharedMemorySize, GEMM_SMEM);

    const int nx = MROWS * DD;   // 16M
    const int nw = DD * DD;      // 4M
    tf32_round_kernel<<<nx / (256 * 4), 256>>>(x, 6, nx);
    tf32_round_w_kernel<<<dim3(nw / (256 * 4), 5), 256>>>(Wq, Wk, Wv, Wg, Wo);

    // merged projections: q (QSCALE) | k | v | eg (sigmoid)
    const int actPack = 1 | (0 << 4) | (0 << 8) | (2 << 12);
    gemm_uni<<<dim3(8 * 4, MROWS / TBM), 256, GEMM_SMEM>>>(6, 7, nullptr, 1, actPack);

    // time-split recurrence: local states -> scan -> replay
    gla_p1<<<dim3(2 * NB, HH, BB), 256>>>();
    gla_p2<<<dim3(4, HH, BB), 256>>>(out + (size_t)MROWS * DD);
    gla_p3<<<dim3(2 * NB, HH, BB), 256>>>();

    // layernorm into g_q (tf32-rounded), then output projection into d_out
    ln_kernel<<<MROWS, 256>>>(gamma, beta);
    gemm_uni<<<dim3(8, MROWS / TBM), 256, GEMM_SMEM>>>(1, 11, out, 0, 0);
}

// round 15
// speedup vs baseline: 1.0604x; 1.0604x over previous
#include <cuda_runtime.h>
#include <math.h>
#include <stdint.h>

// Problem constants
#define BB  2
#define LL  4096
#define DD  2048
#define HH  16
#define KK  128
#define VV  128
#define MROWS (BB*LL)          // 8192
#define QSCALE 0.08838834764831845f   // 128^-0.5
#define LNEPS 1e-5f

// recurrence time-split
#define NB  32
#define TB  (LL/NB)            // 128
#define NBH (BB*HH)            // 32

// GEMM tiling (round-13 proven): CTA tile 128x256, BK=32, 2 stages -> 2 CTAs/SM
#define TBM 128
#define TBN 256
#define TBK 32

#define TSTAGES 2
#define A_STAGE_BYTES (TBM*TBK*4)     // 16384
#define B_STAGE_BYTES (TBN*TBK*4)     // 32768
#define STAGE_BYTES   (A_STAGE_BYTES + B_STAGE_BYTES)   // 49152
#define TC_SMEM       (TSTAGES*STAGE_BYTES + 1024)      // 99328

// fallback (correctness-only) smem
#define PADK 36
#define MMA_SMEM ((TBM + TBN) * PADK * 4)               // 55296

#define GEMM_SMEM (TC_SMEM > MMA_SMEM ? TC_SMEM : MMA_SMEM)

// tcgen05 idesc: dtype=F32(1)<<4 | atype=TF32(2)<<7 | btype=TF32(2)<<10 | (N/8)<<17 | (M/16)<<24
#define IDESC_TF32 ((1u<<4) | (2u<<7) | (2u<<10) | ((TBN/8)<<17) | ((TBM/16)<<24))
#define DESC_BASE_SW128 ( (2ull<<61) | (1ull<<46) | (64ull<<32) | (1ull<<16) )

#if defined(__CUDA_ARCH_FEAT_SM103_ALL) || defined(__CUDA_ARCH_FEAT_SM100_ALL)
#define TC_PATH 1
#else
#define TC_PATH 0
#endif

// -------------------- scratch --------------------
__device__ float g_q [(size_t)MROWS * DD];
__device__ float g_k [(size_t)MROWS * DD];
__device__ float g_v [(size_t)MROWS * DD];
__device__ float g_eg[(size_t)MROWS * DD];
__device__ float g_y [(size_t)MROWS * DD];
__device__ float g_xt[(size_t)MROWS * DD];
__device__ float g_w [5][(size_t)DD * DD];
__device__ float g_sloc  [(size_t)NB * NBH * KK * VV];
__device__ float g_sstart[(size_t)NB * NBH * KK * VV];
__device__ float g_dec   [(size_t)NB * NBH * KK];

__device__ __forceinline__ float* pick_buf(int sel) {
    switch (sel) {
        case 1: return g_q;
        case 2: return g_k;
        case 3: return g_v;
        case 4: return g_eg;
        case 5: return g_y;
        case 6: return g_xt;
        default: return g_w[sel - 7];
    }
}

// -------------------- tf32 rounding pre-pass --------------------
__device__ __forceinline__ float tf32_rna(float f) {
    uint32_t u;
    asm("cvt.rna.tf32.f32 %0, %1;" : "=r"(u) : "f"(f));
    return __uint_as_float(u);
}

__global__ __launch_bounds__(256)
void tf32_round_kernel(const float* __restrict__ in, int outsel, int n)
{
    float* out = pick_buf(outsel);
    int i = (blockIdx.x * 256 + threadIdx.x) * 4;
    if (i < n) {
        float4 v = *(const float4*)(in + i);
        v.x = tf32_rna(v.x); v.y = tf32_rna(v.y);
        v.z = tf32_rna(v.z); v.w = tf32_rna(v.w);
        *(float4*)(out + i) = v;
    }
}

__global__ __launch_bounds__(256)
void tf32_round_w_kernel(const float* __restrict__ w0, const float* __restrict__ w1,
                         const float* __restrict__ w2, const float* __restrict__ w3,
                         const float* __restrict__ w4)
{
    const float* in;
    switch (blockIdx.y) {
        case 0: in = w0; break;
        case 1: in = w1; break;
        case 2: in = w2; break;
        case 3: in = w3; break;
        default: in = w4; break;
    }
    float* out = g_w[blockIdx.y];
    int i = (blockIdx.x * 256 + threadIdx.x) * 4;
    float4 v = *(const float4*)(in + i);
    v.x = tf32_rna(v.x); v.y = tf32_rna(v.y);
    v.z = tf32_rna(v.z); v.w = tf32_rna(v.w);
    *(float4*)(out + i) = v;
}

// -------------------- common helpers --------------------
__device__ __forceinline__ uint32_t smem_u32(const void* p) {
    return (uint32_t)__cvta_generic_to_shared(p);
}
__device__ __forceinline__ void cp16(uint32_t sa, const float* g) {
    asm volatile("cp.async.cg.shared.global [%0], [%1], 16;\n" :: "r"(sa), "l"(g));
}

#if TC_PATH
__device__ __forceinline__ void mbar_init(uint32_t a, uint32_t cnt) {
    asm volatile("mbarrier.init.shared.b64 [%0], %1;" :: "r"(a), "r"(cnt) : "memory");
}
__device__ __forceinline__ void mbar_wait(uint32_t a, uint32_t parity) {
    asm volatile(
        "{\n\t.reg .pred P;\n\t"
        "WLOOP:\n\t"
        "mbarrier.try_wait.parity.shared.b64 P, [%0], %1;\n\t"
        "@P bra.uni WDONE;\n\t"
        "bra.uni WLOOP;\n\t"
        "WDONE:\n\t}"
        :: "r"(a), "r"(parity) : "memory");
}
__device__ __forceinline__ void mma_tf32_tc(uint32_t d, uint64_t ad, uint64_t bd,
                                            uint32_t idesc, uint32_t en) {
    asm volatile(
        "{\n\t.reg .pred p;\n\t"
        "setp.ne.u32 p, %4, 0;\n\t"
        "tcgen05.mma.cta_group::1.kind::tf32 [%0], %1, %2, %3, {%5,%5,%5,%5}, p;\n\t"
        "}"
        :: "r"(d), "l"(ad), "l"(bd), "r"(idesc), "r"(en), "r"(0u) : "memory");
}
__device__ __forceinline__ void tc_commit(uint32_t mbar) {
    asm volatile(
        "tcgen05.commit.cta_group::1.mbarrier::arrive::one.shared::cluster.b64 [%0];"
        :: "r"(mbar) : "memory");
}
#else
__device__ __forceinline__ void mma_tf32(float* c, const uint32_t* a, const uint32_t* b)
{
    asm volatile(
        "mma.sync.aligned.m16n8k8.row.col.f32.tf32.tf32.f32 "
        "{%0,%1,%2,%3},{%4,%5,%6,%7},{%8,%9},{%0,%1,%2,%3};\n"
        : "+f"(c[0]), "+f"(c[1]), "+f"(c[2]), "+f"(c[3])
        : "r"(a[0]), "r"(a[1]), "r"(a[2]), "r"(a[3]), "r"(b[0]), "r"(b[1]));
}
#endif

// -------------------- unified GEMM (round-13 proven): C = act(A @ B^T) ----------
// grid.x = 8 * nproj (bn index in low 3 bits), grid.y = M/128, 256 threads.
__global__ __launch_bounds__(256, 2)
void gemm_uni(int Asel, int Bsel0, float* __restrict__ Cext, int Csel0, int actPack)
{
    extern __shared__ float dsm[];

    const int bnIdx = blockIdx.x & 7;
    const int proj  = blockIdx.x >> 3;

    const float* A = (const float*)pick_buf(Asel);
    const float* B = (const float*)pick_buf(Bsel0 + proj);
    float*       C = Csel0 ? pick_buf(Csel0 + proj) : Cext;
    const int mode = (actPack >> (4 * proj)) & 15;

    const int bm = blockIdx.y * TBM;
    const int bn = bnIdx * TBN;

    const int tid  = threadIdx.x;
    const int warp = tid >> 5, lane = tid & 31;

#if TC_PATH
    __shared__ __align__(8) unsigned long long s_mbar[TSTAGES + 1];
    __shared__ uint32_t s_tmem[1];

    const uint32_t rawb = smem_u32(dsm);
    const uint32_t smb  = (rawb + 1023u) & ~1023u;

    if (warp == 0) {
        asm volatile(
            "tcgen05.alloc.cta_group::1.sync.aligned.shared::cta.b32 [%0], %1;"
            :: "r"(smem_u32(s_tmem)), "r"(256u) : "memory");
        asm volatile("tcgen05.relinquish_alloc_permit.cta_group::1.sync.aligned;");
    }
    if (tid == 0) {
        #pragma unroll
        for (int i = 0; i < TSTAGES + 1; i++)
            mbar_init(smem_u32(&s_mbar[i]), 1u);
    }
    __syncthreads();
    uint32_t tmem_base;
    asm volatile("ld.shared.b32 %0, [%1];" : "=r"(tmem_base) : "r"(smem_u32(s_tmem)));

    const int lr  = tid >> 3;
    const int seg = tid & 7;

    auto loader = [&](int c) {
        const uint32_t sb = smb + (uint32_t)((c & 1) * STAGE_BYTES);
        const float* Ab = A + (size_t)bm * DD + c * TBK;
        #pragma unroll
        for (int i = 0; i < 4; i++) {
            const int row = lr + 32 * i;
            const uint32_t sw = (uint32_t)row * 128u + (uint32_t)((seg ^ (row & 7)) * 16);
            cp16(sb + sw, Ab + (size_t)row * DD + seg * 4);
        }
        const uint32_t bbB = sb + A_STAGE_BYTES;
        const float* Bb = B + (size_t)bn * DD + c * TBK;
        #pragma unroll
        for (int i = 0; i < 8; i++) {
            const int row = lr + 32 * i;
            const uint32_t sw = (uint32_t)row * 128u + (uint32_t)((seg ^ (row & 7)) * 16);
            cp16(bbB + sw, Bb + (size_t)row * DD + seg * 4);
        }
        asm volatile("cp.async.commit_group;\n");
    };

    loader(0); loader(1);

    const int nk = DD / TBK;   // 64
    for (int c = 0; c < nk; c++) {
        asm volatile("cp.async.wait_group 1;\n");
        __syncthreads();

        if (tid == 0) {
            asm volatile("fence.proxy.async.shared::cta;" ::: "memory");
            const uint32_t sb = smb + (uint32_t)((c & 1) * STAGE_BYTES);
            const uint64_t ad = DESC_BASE_SW128 | (uint64_t)((sb >> 4) & 0x3FFF);
            const uint64_t bd = DESC_BASE_SW128 | (uint64_t)(((sb + A_STAGE_BYTES) >> 4) & 0x3FFF);
            #pragma unroll
            for (int k = 0; k < 4; k++)
                mma_tf32_tc(tmem_base, ad + 2 * k, bd + 2 * k, IDESC_TF32,
                            (c > 0 || k > 0) ? 1u : 0u);
            tc_commit(smem_u32(&s_mbar[c & 1]));
        }

        if (c + 2 < nk) {
            mbar_wait(smem_u32(&s_mbar[c & 1]), (uint32_t)((c >> 1) & 1));
            loader(c + 2);
        } else {
            asm volatile("cp.async.commit_group;\n");
        }
    }

    if (tid == 0) tc_commit(smem_u32(&s_mbar[TSTAGES]));
    __syncthreads();
    mbar_wait(smem_u32(&s_mbar[TSTAGES]), 0u);
    asm volatile("tcgen05.fence::after_thread_sync;" ::: "memory");

    const int sub = warp & 3;
    const int cb0 = (warp >> 2) * 128;
    const int row = bm + sub * 32 + lane;
    #pragma unroll
    for (int cb = 0; cb < 128; cb += 32) {
        uint32_t r[32];
        asm volatile(
            "tcgen05.ld.sync.aligned.32x32b.x32.b32 "
            "{%0,%1,%2,%3,%4,%5,%6,%7,%8,%9,%10,%11,%12,%13,%14,%15,"
            "%16,%17,%18,%19,%20,%21,%22,%23,%24,%25,%26,%27,%28,%29,%30,%31}, [%32];"
            : "=r"(r[0]),"=r"(r[1]),"=r"(r[2]),"=r"(r[3]),"=r"(r[4]),"=r"(r[5]),"=r"(r[6]),"=r"(r[7]),
              "=r"(r[8]),"=r"(r[9]),"=r"(r[10]),"=r"(r[11]),"=r"(r[12]),"=r"(r[13]),"=r"(r[14]),"=r"(r[15]),
              "=r"(r[16]),"=r"(r[17]),"=r"(r[18]),"=r"(r[19]),"=r"(r[20]),"=r"(r[21]),"=r"(r[22]),"=r"(r[23]),
              "=r"(r[24]),"=r"(r[25]),"=r"(r[26]),"=r"(r[27]),"=r"(r[28]),"=r"(r[29]),"=r"(r[30]),"=r"(r[31])
            : "r"(tmem_base + cb0 + cb));
        asm volatile("tcgen05.wait::ld.sync.aligned;" ::: "memory");

        float* Crow = C + (size_t)row * DD + bn + cb0 + cb;
        #pragma unroll
        for (int e = 0; e < 32; e += 4) {
            float o[4];
            #pragma unroll
            for (int t = 0; t < 4; t++) {
                float vv = __uint_as_float(r[e + t]);
                if (mode == 1) vv *= QSCALE;
                else if (mode == 2) vv = 1.0f / (1.0f + __expf(-vv));
                o[t] = vv;
            }
            *(float4*)(Crow + e) = make_float4(o[0], o[1], o[2], o[3]);
        }
    }

    __syncthreads();
    if (warp == 0) {
        asm volatile("tcgen05.dealloc.cta_group::1.sync.aligned.b32 %0, %1;"
                     :: "r"(tmem_base), "r"(256u));
    }

#else
    // ====== mma.sync fallback (correctness-only; never runs on sm_103a) ======
    const int wm  = (warp >> 2) * 64;
    const int wn  = (warp & 3) * 64;
    const int grp = lane >> 2, t4 = lane & 3;

    const int lrow = tid >> 3;
    const int lk   = (tid & 7) * 4;

    float acc[4][8][4];
    #pragma unroll
    for (int i = 0; i < 4; i++)
        #pragma unroll
        for (int j = 0; j < 8; j++)
            #pragma unroll
            for (int e = 0; e < 4; e++) acc[i][j][e] = 0.f;

    float* Asm = dsm;
    float* Bsm = dsm + TBM * PADK;

    for (int kt = 0; kt < DD; kt += TBK) {
        __syncthreads();
        #pragma unroll
        for (int i = 0; i < 4; i++) {
            const int row = lrow + 32 * i;
            const float4 av = *(const float4*)(A + (size_t)(bm + row) * DD + kt + lk);
            *(float4*)&Asm[row * PADK + lk] = av;
        }
        #pragma unroll
        for (int i = 0; i < 8; i++) {
            const int row = lrow + 32 * i;
            const float4 bv = *(const float4*)(B + (size_t)(bn + row) * DD + kt + lk);
            *(float4*)&Bsm[row * PADK + lk] = bv;
        }
        __syncthreads();

        #pragma unroll
        for (int k8 = 0; k8 < TBK; k8 += 8) {
            uint32_t a[4][4], b[8][2];
            #pragma unroll
            for (int i = 0; i < 4; i++) {
                const float* ap = Asm + (wm + i * 16 + grp) * PADK + k8 + t4;
                a[i][0] = __float_as_uint(ap[0]);
                a[i][1] = __float_as_uint(ap[8 * PADK]);
                a[i][2] = __float_as_uint(ap[4]);
                a[i][3] = __float_as_uint(ap[8 * PADK + 4]);
            }
            #pragma unroll
            for (int j = 0; j < 8; j++) {
                const float* bp = Bsm + (wn + j * 8 + grp) * PADK + k8 + t4;
                b[j][0] = __float_as_uint(bp[0]);
                b[j][1] = __float_as_uint(bp[4]);
            }
            #pragma unroll
            for (int i = 0; i < 4; i++)
                #pragma unroll
                for (int j = 0; j < 8; j++)
                    mma_tf32(acc[i][j], a[i], b[j]);
        }
    }

    #pragma unroll
    for (int i = 0; i < 4; i++) {
        const int r0 = bm + wm + i * 16 + grp;
        #pragma unroll
        for (int j = 0; j < 8; j++) {
            const int c0 = bn + wn + j * 8 + t4 * 2;
            float o[4];
            #pragma unroll
            for (int e = 0; e < 4; e++) {
                float vv = acc[i][j][e];
                if (mode == 1) vv *= QSCALE;
                else if (mode == 2) vv = 1.0f / (1.0f + __expf(-vv));
                o[e] = vv;
            }
            *(float2*)&C[(size_t)r0 * DD + c0]       = make_float2(o[0], o[1]);
            *(float2*)&C[(size_t)(r0 + 8) * DD + c0] = make_float2(o[2], o[3]);
        }
    }
#endif
}

// ==================== time-split GLA recurrence ====================

// Phase 1 (k-sliced warps, round-13 proven).
__global__ __launch_bounds__(256, 2)
void gla_p1()
{
    const int lane = threadIdx.x & 31;
    const int w    = threadIdx.x >> 5;
    const int kl   = lane & 3;
    const int vl   = lane >> 2;
    const int vc   = blockIdx.x & 1;
    const int blk  = blockIdx.x >> 1;
    const int h    = blockIdx.y;
    const int b    = blockIdx.z;
    const int kofs = w * 16 + kl * 4;
    const int vabs = vc * 64 + vl * 8;

    const size_t base = ((size_t)b * LL + (size_t)blk * TB) * DD + (size_t)h * KK;
    const float* kp = g_k  + base + kofs;
    const float* gp = g_eg + base + kofs;
    const float* vp = g_v  + base + vabs;

    float S[4][8];
    float dp[4];
    #pragma unroll
    for (int i = 0; i < 4; i++) {
        dp[i] = 1.f;
        #pragma unroll
        for (int j = 0; j < 8; j++) S[i][j] = 0.f;
    }

    struct F { float4 k, g, v0, v1; } f[3];
    auto ld = [&](F& fr, int t) {
        const size_t off = (size_t)t * DD;
        fr.k  = *(const float4*)(kp + off);
        fr.g  = *(const float4*)(gp + off);
        fr.v0 = *(const float4*)(vp + off);
        fr.v1 = *(const float4*)(vp + off + 4);
    };
    ld(f[0], 0); ld(f[1], 1);

    #pragma unroll 3
    for (int t = 0; t < TB; ++t) {
        const int tn = (t + 2 < TB) ? (t + 2) : (TB - 1);
        ld(f[(t + 2) % 3], tn);

        const F& c = f[t % 3];
        float k[4] = {c.k.x, c.k.y, c.k.z, c.k.w};
        float g[4] = {c.g.x, c.g.y, c.g.z, c.g.w};
        float v[8] = {c.v0.x, c.v0.y, c.v0.z, c.v0.w, c.v1.x, c.v1.y, c.v1.z, c.v1.w};

        #pragma unroll
        for (int i = 0; i < 4; i++) {
            dp[i] *= g[i];
            #pragma unroll
            for (int j = 0; j < 8; j++)
                S[i][j] = fmaf(S[i][j], g[i], k[i] * v[j]);
        }
    }

    const size_t bh = (size_t)b * HH + h;
    const size_t so = (((size_t)blk * NBH + bh) * KK + kofs) * VV + vabs;
    #pragma unroll
    for (int i = 0; i < 4; i++) {
        *(float4*)&g_sloc[so + (size_t)i * VV]     = make_float4(S[i][0], S[i][1], S[i][2], S[i][3]);
        *(float4*)&g_sloc[so + (size_t)i * VV + 4] = make_float4(S[i][4], S[i][5], S[i][6], S[i][7]);
    }
    if (vl == 0 && vc == 0) {
        const size_t dofs = ((size_t)blk * NBH + bh) * KK + kofs;
        #pragma unroll
        for (int i = 0; i < 4; i++) g_dec[dofs + i] = dp[i];
    }
}

// Phase 2: sequential combine over NB blocks (parallelism doubled: k split over CTAs).
// grid (8, H, B): blockIdx.x = (kh << 2) | vchunk. 256 thr = 8 kq-groups(8k) x 32 vslots(1v).
__global__ __launch_bounds__(256)
void gla_p2(float* __restrict__ out_state)
{
    const int tid   = threadIdx.x;
    const int vslot = tid & 31;          // 32 consecutive v
    const int kq    = tid >> 5;          // 8 groups of 8 k
    const int vchunk = blockIdx.x & 3;
    const int kh     = blockIdx.x >> 2;  // k half
    const int kofs  = kh * 64 + kq * 8;
    const int vabs  = vchunk * 32 + vslot;
    const int h     = blockIdx.y;
    const int b     = blockIdx.z;
    const size_t bh = (size_t)b * HH + h;

    float R[8];
    #pragma unroll
    for (int i = 0; i < 8; i++) R[i] = 0.f;

    for (int i = 0; i < NB; i++) {
        const size_t so   = (((size_t)i * NBH + bh) * KK + kofs) * VV + vabs;
        const size_t dofs = ((size_t)i * NBH + bh) * KK + kofs;
        #pragma unroll
        for (int j = 0; j < 8; j++) {
            g_sstart[so + (size_t)j * VV] = R[j];
            const float sl = g_sloc[so + (size_t)j * VV];
            const float d  = g_dec[dofs + j];
            R[j] = fmaf(d, R[j], sl);
        }
    }

    const size_t fsbase = (bh * KK + kofs) * VV + vabs;
    #pragma unroll
    for (int j = 0; j < 8; j++)
        out_state[fsbase + (size_t)j * VV] = R[j];
}

// Phase 3 (Layout D, round-12 proven).
__global__ __launch_bounds__(256, 2)
void gla_p3()
{
    const int lane = threadIdx.x & 31;
    const int w    = threadIdx.x >> 5;
    const int vc   = blockIdx.x & 1;
    const int blk  = blockIdx.x >> 1;
    const int vabs = vc * 64 + w * 8;
    const int h    = blockIdx.y;
    const int b    = blockIdx.z;

    const size_t base = ((size_t)b * LL + (size_t)blk * TB) * DD + (size_t)h * KK;
    const float* qp = g_q  + base + lane * 4;
    const float* kp = g_k  + base + lane * 4;
    const float* gp = g_eg + base + lane * 4;
    const float* vp = g_v  + base + vabs;
    float*       yp = g_y  + base + vabs;

    const size_t bh = (size_t)b * HH + h;
    const size_t so = (((size_t)blk * NBH + bh) * KK + lane * 4) * VV + vabs;

    float S[4][8];
    #pragma unroll
    for (int i = 0; i < 4; i++) {
        const float4 s0 = *(const float4*)&g_sstart[so + (size_t)i * VV];
        const float4 s1 = *(const float4*)&g_sstart[so + (size_t)i * VV + 4];
        S[i][0] = s0.x; S[i][1] = s0.y; S[i][2] = s0.z; S[i][3] = s0.w;
        S[i][4] = s1.x; S[i][5] = s1.y; S[i][6] = s1.z; S[i][7] = s1.w;
    }

    struct F { float4 q, k, g, v0, v1; } f[3];
    auto ld = [&](F& fr, int t) {
        const size_t off = (size_t)t * DD;
        fr.q  = *(const float4*)(qp + off);
        fr.k  = *(const float4*)(kp + off);
        fr.g  = *(const float4*)(gp + off);
        fr.v0 = *(const float4*)(vp + off);
        fr.v1 = *(const float4*)(vp + off + 4);
    };
    ld(f[0], 0); ld(f[1], 1);

    #pragma unroll 3
    for (int t = 0; t < TB; ++t) {
        const int tn = (t + 2 < TB) ? (t + 2) : (TB - 1);
        ld(f[(t + 2) % 3], tn);

        const F& c = f[t % 3];
        float q[4] = {c.q.x, c.q.y, c.q.z, c.q.w};
        float k[4] = {c.k.x, c.k.y, c.k.z, c.k.w};
        float g[4] = {c.g.x, c.g.y, c.g.z, c.g.w};
        float v[8] = {c.v0.x, c.v0.y, c.v0.z, c.v0.w, c.v1.x, c.v1.y, c.v1.z, c.v1.w};

        float acc[8] = {0.f,0.f,0.f,0.f,0.f,0.f,0.f,0.f};
        #pragma unroll
        for (int i = 0; i < 4; i++) {
            #pragma unroll
            for (int j = 0; j < 8; j++) {
                S[i][j] = fmaf(S[i][j], g[i], k[i] * v[j]);
                acc[j]  = fmaf(q[i], S[i][j], acc[j]);
            }
        }

        #pragma unroll
        for (int m = 1; m <= 16; m <<= 1) {
            #pragma unroll
            for (int j = 0; j < 8; j++)
                acc[j] += __shfl_xor_sync(0xffffffffu, acc[j], m);
        }
        if (lane == 0) {
            *(float4*)(yp + (size_t)t * DD)     = make_float4(acc[0], acc[1], acc[2], acc[3]);
            *(float4*)(yp + (size_t)t * DD + 4) = make_float4(acc[4], acc[5], acc[6], acc[7]);
        }
    }
}

// -------------------- LayerNorm --------------------
__global__ __launch_bounds__(256)
void ln_kernel(const float* __restrict__ gamma, const float* __restrict__ beta)
{
    const int row = blockIdx.x;
    const float* yr   = g_y + (size_t)row * DD;
    float*       orow = g_q + (size_t)row * DD;
    const int c0 = threadIdx.x * 8;

    const float4 v0 = *(const float4*)(yr + c0);
    const float4 v1 = *(const float4*)(yr + c0 + 4);
    float vals[8] = {v0.x, v0.y, v0.z, v0.w, v1.x, v1.y, v1.z, v1.w};

    float s = 0.f, s2 = 0.f;
    #pragma unroll
    for (int i = 0; i < 8; i++) { s += vals[i]; s2 = fmaf(vals[i], vals[i], s2); }

    #pragma unroll
    for (int m = 16; m >= 1; m >>= 1) {
        s  += __shfl_xor_sync(0xffffffffu, s,  m);
        s2 += __shfl_xor_sync(0xffffffffu, s2, m);
    }
    __shared__ float ws[8], ws2[8];
    const int warp = threadIdx.x >> 5;
    if ((threadIdx.x & 31) == 0) { ws[warp] = s; ws2[warp] = s2; }
    __syncthreads();
    float ts = 0.f, ts2 = 0.f;
    #pragma unroll
    for (int i = 0; i < 8; i++) { ts += ws[i]; ts2 += ws2[i]; }

    const float mu  = ts * (1.0f / DD);
    const float var = ts2 * (1.0f / DD) - mu * mu;
    const float r   = rsqrtf(var + LNEPS);

    const float4 ga0 = *(const float4*)(gamma + c0);
    const float4 ga1 = *(const float4*)(gamma + c0 + 4);
    const float4 be0 = *(const float4*)(beta + c0);
    const float4 be1 = *(const float4*)(beta + c0 + 4);
    float gm[8] = {ga0.x, ga0.y, ga0.z, ga0.w, ga1.x, ga1.y, ga1.z, ga1.w};
    float bt[8] = {be0.x, be0.y, be0.z, be0.w, be1.x, be1.y, be1.z, be1.w};

    float o[8];
    #pragma unroll
    for (int i = 0; i < 8; i++)
        o[i] = tf32_rna(fmaf((vals[i] - mu) * r, gm[i], bt[i]));
    *(float4*)(orow + c0)     = make_float4(o[0], o[1], o[2], o[3]);
    *(float4*)(orow + c0 + 4) = make_float4(o[4], o[5], o[6], o[7]);
}

// -------------------- launch --------------------
extern "C" void kernel_launch(void* const* d_in, const int* in_sizes, int n_in,
                              void* d_out, int out_size)
{
    const float* x     = (const float*)d_in[0];
    const float* Wq    = (const float*)d_in[1];
    const float* Wk    = (const float*)d_in[2];
    const float* Wv    = (const float*)d_in[3];
    const float* Wg    = (const float*)d_in[4];
    const float* Wo    = (const float*)d_in[5];
    const float* gamma = (const float*)d_in[6];
    const float* beta  = (const float*)d_in[7];
    float* out = (float*)d_out;

    cudaFuncSetAttribute(gemm_uni, cudaFuncAttributeMaxDynamicSharedMemorySize, GEMM_SMEM);

    const int nx = MROWS * DD;   // 16M
    const int nw = DD * DD;      // 4M
    tf32_round_kernel<<<nx / (256 * 4), 256>>>(x, 6, nx);
    tf32_round_w_kernel<<<dim3(nw / (256 * 4), 5), 256>>>(Wq, Wk, Wv, Wg, Wo);

    // merged projections: q (QSCALE) | k | v | eg (sigmoid)
    const int actPack = 1 | (0 << 4) | (0 << 8) | (2 << 12);
    gemm_uni<<<dim3(8 * 4, MROWS / TBM), 256, GEMM_SMEM>>>(6, 7, nullptr, 1, actPack);

    // time-split recurrence: local states -> scan -> replay
    gla_p1<<<dim3(2 * NB, HH, BB), 256>>>();
    gla_p2<<<dim3(8, HH, BB), 256>>>(out + (size_t)MROWS * DD);
    gla_p3<<<dim3(2 * NB, HH, BB), 256>>>();

    // layernorm into g_q (tf32-rounded), then output projection into d_out
    ln_kernel<<<MROWS, 256>>>(gamma, beta);
    gemm_uni<<<dim3(8, MROWS / TBM), 256, GEMM_SMEM>>>(1, 11, out, 0, 0);
}

// round 16
// speedup vs baseline: 1.1770x; 1.1100x over previous
#include <cuda_runtime.h>
#include <math.h>
#include <stdint.h>

// Problem constants
#define BB  2
#define LL  4096
#define DD  2048
#define HH  16
#define KK  128
#define VV  128
#define MROWS (BB*LL)          // 8192
#define QSCALE 0.08838834764831845f   // 128^-0.5
#define LNEPS 1e-5f

// recurrence time-split
#define NB  32
#define TB  (LL/NB)            // 128
#define NBH (BB*HH)            // 32

// GEMM tiling (round-13 proven): CTA tile 128x256, BK=32, 2 stages -> 2 CTAs/SM
#define TBM 128
#define TBN 256
#define TBK 32

#define TSTAGES 2
#define A_STAGE_BYTES (TBM*TBK*4)     // 16384
#define B_STAGE_BYTES (TBN*TBK*4)     // 32768
#define STAGE_BYTES   (A_STAGE_BYTES + B_STAGE_BYTES)   // 49152
#define TC_SMEM       (TSTAGES*STAGE_BYTES + 1024)      // 99328

// fallback (correctness-only) smem
#define PADK 36
#define MMA_SMEM ((TBM + TBN) * PADK * 4)               // 55296

#define GEMM_SMEM (TC_SMEM > MMA_SMEM ? TC_SMEM : MMA_SMEM)

// tcgen05 idesc: dtype=F32(1)<<4 | atype=TF32(2)<<7 | btype=TF32(2)<<10 | (N/8)<<17 | (M/16)<<24
#define IDESC_TF32 ((1u<<4) | (2u<<7) | (2u<<10) | ((TBN/8)<<17) | ((TBM/16)<<24))
#define DESC_BASE_SW128 ( (2ull<<61) | (1ull<<46) | (64ull<<32) | (1ull<<16) )

#if defined(__CUDA_ARCH_FEAT_SM103_ALL) || defined(__CUDA_ARCH_FEAT_SM100_ALL)
#define TC_PATH 1
#else
#define TC_PATH 0
#endif

// -------------------- scratch --------------------
__device__ float g_q [(size_t)MROWS * DD];
__device__ float g_k [(size_t)MROWS * DD];
__device__ float g_v [(size_t)MROWS * DD];
__device__ float g_eg[(size_t)MROWS * DD];
__device__ float g_y [(size_t)MROWS * DD];
__device__ float g_xt[(size_t)MROWS * DD];
__device__ float g_w [5][(size_t)DD * DD];
__device__ float g_sloc  [(size_t)NB * NBH * KK * VV];
__device__ float g_sstart[(size_t)NB * NBH * KK * VV];
__device__ float g_dec   [(size_t)NB * NBH * KK];

__device__ __forceinline__ float* pick_buf(int sel) {
    switch (sel) {
        case 1: return g_q;
        case 2: return g_k;
        case 3: return g_v;
        case 4: return g_eg;
        case 5: return g_y;
        case 6: return g_xt;
        default: return g_w[sel - 7];
    }
}

// -------------------- tf32 rounding pre-pass --------------------
__device__ __forceinline__ float tf32_rna(float f) {
    uint32_t u;
    asm("cvt.rna.tf32.f32 %0, %1;" : "=r"(u) : "f"(f));
    return __uint_as_float(u);
}

__global__ __launch_bounds__(256)
void tf32_round_kernel(const float* __restrict__ in, int outsel, int n)
{
    float* out = pick_buf(outsel);
    int i = (blockIdx.x * 256 + threadIdx.x) * 4;
    if (i < n) {
        float4 v = *(const float4*)(in + i);
        v.x = tf32_rna(v.x); v.y = tf32_rna(v.y);
        v.z = tf32_rna(v.z); v.w = tf32_rna(v.w);
        *(float4*)(out + i) = v;
    }
}

__global__ __launch_bounds__(256)
void tf32_round_w_kernel(const float* __restrict__ w0, const float* __restrict__ w1,
                         const float* __restrict__ w2, const float* __restrict__ w3,
                         const float* __restrict__ w4)
{
    const float* in;
    switch (blockIdx.y) {
        case 0: in = w0; break;
        case 1: in = w1; break;
        case 2: in = w2; break;
        case 3: in = w3; break;
        default: in = w4; break;
    }
    float* out = g_w[blockIdx.y];
    int i = (blockIdx.x * 256 + threadIdx.x) * 4;
    float4 v = *(const float4*)(in + i);
    v.x = tf32_rna(v.x); v.y = tf32_rna(v.y);
    v.z = tf32_rna(v.z); v.w = tf32_rna(v.w);
    *(float4*)(out + i) = v;
}

// -------------------- common helpers --------------------
__device__ __forceinline__ uint32_t smem_u32(const void* p) {
    return (uint32_t)__cvta_generic_to_shared(p);
}
__device__ __forceinline__ void cp16(uint32_t sa, const float* g) {
    asm volatile("cp.async.cg.shared.global [%0], [%1], 16;\n" :: "r"(sa), "l"(g));
}

#if TC_PATH
__device__ __forceinline__ void mbar_init(uint32_t a, uint32_t cnt) {
    asm volatile("mbarrier.init.shared.b64 [%0], %1;" :: "r"(a), "r"(cnt) : "memory");
}
__device__ __forceinline__ void mbar_wait(uint32_t a, uint32_t parity) {
    asm volatile(
        "{\n\t.reg .pred P;\n\t"
        "WLOOP:\n\t"
        "mbarrier.try_wait.parity.shared.b64 P, [%0], %1;\n\t"
        "@P bra.uni WDONE;\n\t"
        "bra.uni WLOOP;\n\t"
        "WDONE:\n\t}"
        :: "r"(a), "r"(parity) : "memory");
}
__device__ __forceinline__ void mma_tf32_tc(uint32_t d, uint64_t ad, uint64_t bd,
                                            uint32_t idesc, uint32_t en) {
    asm volatile(
        "{\n\t.reg .pred p;\n\t"
        "setp.ne.u32 p, %4, 0;\n\t"
        "tcgen05.mma.cta_group::1.kind::tf32 [%0], %1, %2, %3, {%5,%5,%5,%5}, p;\n\t"
        "}"
        :: "r"(d), "l"(ad), "l"(bd), "r"(idesc), "r"(en), "r"(0u) : "memory");
}
__device__ __forceinline__ void tc_commit(uint32_t mbar) {
    asm volatile(
        "tcgen05.commit.cta_group::1.mbarrier::arrive::one.shared::cluster.b64 [%0];"
        :: "r"(mbar) : "memory");
}
#else
__device__ __forceinline__ void mma_tf32(float* c, const uint32_t* a, const uint32_t* b)
{
    asm volatile(
        "mma.sync.aligned.m16n8k8.row.col.f32.tf32.tf32.f32 "
        "{%0,%1,%2,%3},{%4,%5,%6,%7},{%8,%9},{%0,%1,%2,%3};\n"
        : "+f"(c[0]), "+f"(c[1]), "+f"(c[2]), "+f"(c[3])
        : "r"(a[0]), "r"(a[1]), "r"(a[2]), "r"(a[3]), "r"(b[0]), "r"(b[1]));
}
#endif

// -------------------- unified GEMM (round-13 proven): C = act(A @ B^T) ----------
// grid.x = 8 * nproj (bn index in low 3 bits), grid.y = M/128, 256 threads.
__global__ __launch_bounds__(256, 2)
void gemm_uni(int Asel, int Bsel0, float* __restrict__ Cext, int Csel0, int actPack)
{
    extern __shared__ float dsm[];

    const int bnIdx = blockIdx.x & 7;
    const int proj  = blockIdx.x >> 3;

    const float* A = (const float*)pick_buf(Asel);
    const float* B = (const float*)pick_buf(Bsel0 + proj);
    float*       C = Csel0 ? pick_buf(Csel0 + proj) : Cext;
    const int mode = (actPack >> (4 * proj)) & 15;

    const int bm = blockIdx.y * TBM;
    const int bn = bnIdx * TBN;

    const int tid  = threadIdx.x;
    const int warp = tid >> 5, lane = tid & 31;

#if TC_PATH
    __shared__ __align__(8) unsigned long long s_mbar[TSTAGES + 1];
    __shared__ uint32_t s_tmem[1];

    const uint32_t rawb = smem_u32(dsm);
    const uint32_t smb  = (rawb + 1023u) & ~1023u;

    if (warp == 0) {
        asm volatile(
            "tcgen05.alloc.cta_group::1.sync.aligned.shared::cta.b32 [%0], %1;"
            :: "r"(smem_u32(s_tmem)), "r"(256u) : "memory");
        asm volatile("tcgen05.relinquish_alloc_permit.cta_group::1.sync.aligned;");
    }
    if (tid == 0) {
        #pragma unroll
        for (int i = 0; i < TSTAGES + 1; i++)
            mbar_init(smem_u32(&s_mbar[i]), 1u);
    }
    __syncthreads();
    uint32_t tmem_base;
    asm volatile("ld.shared.b32 %0, [%1];" : "=r"(tmem_base) : "r"(smem_u32(s_tmem)));

    const int lr  = tid >> 3;
    const int seg = tid & 7;

    auto loader = [&](int c) {
        const uint32_t sb = smb + (uint32_t)((c & 1) * STAGE_BYTES);
        const float* Ab = A + (size_t)bm * DD + c * TBK;
        #pragma unroll
        for (int i = 0; i < 4; i++) {
            const int row = lr + 32 * i;
            const uint32_t sw = (uint32_t)row * 128u + (uint32_t)((seg ^ (row & 7)) * 16);
            cp16(sb + sw, Ab + (size_t)row * DD + seg * 4);
        }
        const uint32_t bbB = sb + A_STAGE_BYTES;
        const float* Bb = B + (size_t)bn * DD + c * TBK;
        #pragma unroll
        for (int i = 0; i < 8; i++) {
            const int row = lr + 32 * i;
            const uint32_t sw = (uint32_t)row * 128u + (uint32_t)((seg ^ (row & 7)) * 16);
            cp16(bbB + sw, Bb + (size_t)row * DD + seg * 4);
        }
        asm volatile("cp.async.commit_group;\n");
    };

    loader(0); loader(1);

    const int nk = DD / TBK;   // 64
    for (int c = 0; c < nk; c++) {
        asm volatile("cp.async.wait_group 1;\n");
        __syncthreads();

        if (tid == 0) {
            asm volatile("fence.proxy.async.shared::cta;" ::: "memory");
            const uint32_t sb = smb + (uint32_t)((c & 1) * STAGE_BYTES);
            const uint64_t ad = DESC_BASE_SW128 | (uint64_t)((sb >> 4) & 0x3FFF);
            const uint64_t bd = DESC_BASE_SW128 | (uint64_t)(((sb + A_STAGE_BYTES) >> 4) & 0x3FFF);
            #pragma unroll
            for (int k = 0; k < 4; k++)
                mma_tf32_tc(tmem_base, ad + 2 * k, bd + 2 * k, IDESC_TF32,
                            (c > 0 || k > 0) ? 1u : 0u);
            tc_commit(smem_u32(&s_mbar[c & 1]));
        }

        if (c + 2 < nk) {
            mbar_wait(smem_u32(&s_mbar[c & 1]), (uint32_t)((c >> 1) & 1));
            loader(c + 2);
        } else {
            asm volatile("cp.async.commit_group;\n");
        }
    }

    if (tid == 0) tc_commit(smem_u32(&s_mbar[TSTAGES]));
    __syncthreads();
    mbar_wait(smem_u32(&s_mbar[TSTAGES]), 0u);
    asm volatile("tcgen05.fence::after_thread_sync;" ::: "memory");

    const int sub = warp & 3;
    const int cb0 = (warp >> 2) * 128;
    const int row = bm + sub * 32 + lane;
    #pragma unroll
    for (int cb = 0; cb < 128; cb += 32) {
        uint32_t r[32];
        asm volatile(
            "tcgen05.ld.sync.aligned.32x32b.x32.b32 "
            "{%0,%1,%2,%3,%4,%5,%6,%7,%8,%9,%10,%11,%12,%13,%14,%15,"
            "%16,%17,%18,%19,%20,%21,%22,%23,%24,%25,%26,%27,%28,%29,%30,%31}, [%32];"
            : "=r"(r[0]),"=r"(r[1]),"=r"(r[2]),"=r"(r[3]),"=r"(r[4]),"=r"(r[5]),"=r"(r[6]),"=r"(r[7]),
              "=r"(r[8]),"=r"(r[9]),"=r"(r[10]),"=r"(r[11]),"=r"(r[12]),"=r"(r[13]),"=r"(r[14]),"=r"(r[15]),
              "=r"(r[16]),"=r"(r[17]),"=r"(r[18]),"=r"(r[19]),"=r"(r[20]),"=r"(r[21]),"=r"(r[22]),"=r"(r[23]),
              "=r"(r[24]),"=r"(r[25]),"=r"(r[26]),"=r"(r[27]),"=r"(r[28]),"=r"(r[29]),"=r"(r[30]),"=r"(r[31])
            : "r"(tmem_base + cb0 + cb));
        asm volatile("tcgen05.wait::ld.sync.aligned;" ::: "memory");

        float* Crow = C + (size_t)row * DD + bn + cb0 + cb;
        #pragma unroll
        for (int e = 0; e < 32; e += 4) {
            float o[4];
            #pragma unroll
            for (int t = 0; t < 4; t++) {
                float vv = __uint_as_float(r[e + t]);
                if (mode == 1) vv *= QSCALE;
                else if (mode == 2) vv = 1.0f / (1.0f + __expf(-vv));
                o[t] = vv;
            }
            *(float4*)(Crow + e) = make_float4(o[0], o[1], o[2], o[3]);
        }
    }

    __syncthreads();
    if (warp == 0) {
        asm volatile("tcgen05.dealloc.cta_group::1.sync.aligned.b32 %0, %1;"
                     :: "r"(tmem_base), "r"(256u));
    }

#else
    // ====== mma.sync fallback (correctness-only; never runs on sm_103a) ======
    const int wm  = (warp >> 2) * 64;
    const int wn  = (warp & 3) * 64;
    const int grp = lane >> 2, t4 = lane & 3;

    const int lrow = tid >> 3;
    const int lk   = (tid & 7) * 4;

    float acc[4][8][4];
    #pragma unroll
    for (int i = 0; i < 4; i++)
        #pragma unroll
        for (int j = 0; j < 8; j++)
            #pragma unroll
            for (int e = 0; e < 4; e++) acc[i][j][e] = 0.f;

    float* Asm = dsm;
    float* Bsm = dsm + TBM * PADK;

    for (int kt = 0; kt < DD; kt += TBK) {
        __syncthreads();
        #pragma unroll
        for (int i = 0; i < 4; i++) {
            const int row = lrow + 32 * i;
            const float4 av = *(const float4*)(A + (size_t)(bm + row) * DD + kt + lk);
            *(float4*)&Asm[row * PADK + lk] = av;
        }
        #pragma unroll
        for (int i = 0; i < 8; i++) {
            const int row = lrow + 32 * i;
            const float4 bv = *(const float4*)(B + (size_t)(bn + row) * DD + kt + lk);
            *(float4*)&Bsm[row * PADK + lk] = bv;
        }
        __syncthreads();

        #pragma unroll
        for (int k8 = 0; k8 < TBK; k8 += 8) {
            uint32_t a[4][4], b[8][2];
            #pragma unroll
            for (int i = 0; i < 4; i++) {
                const float* ap = Asm + (wm + i * 16 + grp) * PADK + k8 + t4;
                a[i][0] = __float_as_uint(ap[0]);
                a[i][1] = __float_as_uint(ap[8 * PADK]);
                a[i][2] = __float_as_uint(ap[4]);
                a[i][3] = __float_as_uint(ap[8 * PADK + 4]);
            }
            #pragma unroll
            for (int j = 0; j < 8; j++) {
                const float* bp = Bsm + (wn + j * 8 + grp) * PADK + k8 + t4;
                b[j][0] = __float_as_uint(bp[0]);
                b[j][1] = __float_as_uint(bp[4]);
            }
            #pragma unroll
            for (int i = 0; i < 4; i++)
                #pragma unroll
                for (int j = 0; j < 8; j++)
                    mma_tf32(acc[i][j], a[i], b[j]);
        }
    }

    #pragma unroll
    for (int i = 0; i < 4; i++) {
        const int r0 = bm + wm + i * 16 + grp;
        #pragma unroll
        for (int j = 0; j < 8; j++) {
            const int c0 = bn + wn + j * 8 + t4 * 2;
            float o[4];
            #pragma unroll
            for (int e = 0; e < 4; e++) {
                float vv = acc[i][j][e];
                if (mode == 1) vv *= QSCALE;
                else if (mode == 2) vv = 1.0f / (1.0f + __expf(-vv));
                o[e] = vv;
            }
            *(float2*)&C[(size_t)r0 * DD + c0]       = make_float2(o[0], o[1]);
            *(float2*)&C[(size_t)(r0 + 8) * DD + c0] = make_float2(o[2], o[3]);
        }
    }
#endif
}

// ==================== time-split GLA recurrence ====================

// Phase 1 (k-sliced warps; depth-3 prefetch).
__global__ __launch_bounds__(256, 2)
void gla_p1()
{
    const int lane = threadIdx.x & 31;
    const int w    = threadIdx.x >> 5;
    const int kl   = lane & 3;
    const int vl   = lane >> 2;
    const int vc   = blockIdx.x & 1;
    const int blk  = blockIdx.x >> 1;
    const int h    = blockIdx.y;
    const int b    = blockIdx.z;
    const int kofs = w * 16 + kl * 4;
    const int vabs = vc * 64 + vl * 8;

    const size_t base = ((size_t)b * LL + (size_t)blk * TB) * DD + (size_t)h * KK;
    const float* kp = g_k  + base + kofs;
    const float* gp = g_eg + base + kofs;
    const float* vp = g_v  + base + vabs;

    float S[4][8];
    float dp[4];
    #pragma unroll
    for (int i = 0; i < 4; i++) {
        dp[i] = 1.f;
        #pragma unroll
        for (int j = 0; j < 8; j++) S[i][j] = 0.f;
    }

    struct F { float4 k, g, v0, v1; } f[4];
    auto ld = [&](F& fr, int t) {
        const size_t off = (size_t)t * DD;
        fr.k  = *(const float4*)(kp + off);
        fr.g  = *(const float4*)(gp + off);
        fr.v0 = *(const float4*)(vp + off);
        fr.v1 = *(const float4*)(vp + off + 4);
    };
    ld(f[0], 0); ld(f[1], 1); ld(f[2], 2);

    #pragma unroll 4
    for (int t = 0; t < TB; ++t) {
        const int tn = (t + 3 < TB) ? (t + 3) : (TB - 1);
        ld(f[(t + 3) & 3], tn);

        const F& c = f[t & 3];
        float k[4] = {c.k.x, c.k.y, c.k.z, c.k.w};
        float g[4] = {c.g.x, c.g.y, c.g.z, c.g.w};
        float v[8] = {c.v0.x, c.v0.y, c.v0.z, c.v0.w, c.v1.x, c.v1.y, c.v1.z, c.v1.w};

        #pragma unroll
        for (int i = 0; i < 4; i++) {
            dp[i] *= g[i];
            #pragma unroll
            for (int j = 0; j < 8; j++)
                S[i][j] = fmaf(S[i][j], g[i], k[i] * v[j]);
        }
    }

    const size_t bh = (size_t)b * HH + h;
    const size_t so = (((size_t)blk * NBH + bh) * KK + kofs) * VV + vabs;
    #pragma unroll
    for (int i = 0; i < 4; i++) {
        *(float4*)&g_sloc[so + (size_t)i * VV]     = make_float4(S[i][0], S[i][1], S[i][2], S[i][3]);
        *(float4*)&g_sloc[so + (size_t)i * VV + 4] = make_float4(S[i][4], S[i][5], S[i][6], S[i][7]);
    }
    if (vl == 0 && vc == 0) {
        const size_t dofs = ((size_t)blk * NBH + bh) * KK + kofs;
        #pragma unroll
        for (int i = 0; i < 4; i++) g_dec[dofs + i] = dp[i];
    }
}

// Phase 2 (round-15 proven): k split over CTAs.
__global__ __launch_bounds__(256)
void gla_p2(float* __restrict__ out_state)
{
    const int tid   = threadIdx.x;
    const int vslot = tid & 31;
    const int kq    = tid >> 5;
    const int vchunk = blockIdx.x & 3;
    const int kh     = blockIdx.x >> 2;
    const int kofs  = kh * 64 + kq * 8;
    const int vabs  = vchunk * 32 + vslot;
    const int h     = blockIdx.y;
    const int b     = blockIdx.z;
    const size_t bh = (size_t)b * HH + h;

    float R[8];
    #pragma unroll
    for (int i = 0; i < 8; i++) R[i] = 0.f;

    for (int i = 0; i < NB; i++) {
        const size_t so   = (((size_t)i * NBH + bh) * KK + kofs) * VV + vabs;
        const size_t dofs = ((size_t)i * NBH + bh) * KK + kofs;
        #pragma unroll
        for (int j = 0; j < 8; j++) {
            g_sstart[so + (size_t)j * VV] = R[j];
            const float sl = g_sloc[so + (size_t)j * VV];
            const float d  = g_dec[dofs + j];
            R[j] = fmaf(d, R[j], sl);
        }
    }

    const size_t fsbase = (bh * KK + kofs) * VV + vabs;
    #pragma unroll
    for (int j = 0; j < 8; j++)
        out_state[fsbase + (size_t)j * VV] = R[j];
}

// Phase 3 (Layout D + value-folding reduction, 9 shfl/iter).
__global__ __launch_bounds__(256, 2)
void gla_p3()
{
    const int lane = threadIdx.x & 31;
    const int w    = threadIdx.x >> 5;
    const int vc   = blockIdx.x & 1;
    const int blk  = blockIdx.x >> 1;
    const int vabs = vc * 64 + w * 8;
    const int h    = blockIdx.y;
    const int b    = blockIdx.z;

    const size_t base = ((size_t)b * LL + (size_t)blk * TB) * DD + (size_t)h * KK;
    const float* qp = g_q  + base + lane * 4;
    const float* kp = g_k  + base + lane * 4;
    const float* gp = g_eg + base + lane * 4;
    const float* vp = g_v  + base + vabs;
    float*       yp = g_y  + base + vabs;

    const size_t bh = (size_t)b * HH + h;
    const size_t so = (((size_t)blk * NBH + bh) * KK + lane * 4) * VV + vabs;

    float S[4][8];
    #pragma unroll
    for (int i = 0; i < 4; i++) {
        const float4 s0 = *(const float4*)&g_sstart[so + (size_t)i * VV];
        const float4 s1 = *(const float4*)&g_sstart[so + (size_t)i * VV + 4];
        S[i][0] = s0.x; S[i][1] = s0.y; S[i][2] = s0.z; S[i][3] = s0.w;
        S[i][4] = s1.x; S[i][5] = s1.y; S[i][6] = s1.z; S[i][7] = s1.w;
    }

    // fold helpers: lane bits select which v this lane keeps at each level
    const bool b4 = (lane & 16) != 0;
    const bool b3 = (lane & 8)  != 0;
    const bool b2 = (lane & 4)  != 0;
    const int  vwi = ((lane >> 4) & 1) * 4 + ((lane >> 3) & 1) * 2 + ((lane >> 2) & 1);
    const bool writer = (lane & 3) == 0;

    struct F { float4 q, k, g, v0, v1; } f[3];
    auto ld = [&](F& fr, int t) {
        const size_t off = (size_t)t * DD;
        fr.q  = *(const float4*)(qp + off);
        fr.k  = *(const float4*)(kp + off);
        fr.g  = *(const float4*)(gp + off);
        fr.v0 = *(const float4*)(vp + off);
        fr.v1 = *(const float4*)(vp + off + 4);
    };
    ld(f[0], 0); ld(f[1], 1);

    #pragma unroll 3
    for (int t = 0; t < TB; ++t) {
        const int tn = (t + 2 < TB) ? (t + 2) : (TB - 1);
        ld(f[(t + 2) % 3], tn);

        const F& c = f[t % 3];
        float q[4] = {c.q.x, c.q.y, c.q.z, c.q.w};
        float k[4] = {c.k.x, c.k.y, c.k.z, c.k.w};
        float g[4] = {c.g.x, c.g.y, c.g.z, c.g.w};
        float v[8] = {c.v0.x, c.v0.y, c.v0.z, c.v0.w, c.v1.x, c.v1.y, c.v1.z, c.v1.w};

        float acc[8] = {0.f,0.f,0.f,0.f,0.f,0.f,0.f,0.f};
        #pragma unroll
        for (int i = 0; i < 4; i++) {
            #pragma unroll
            for (int j = 0; j < 8; j++) {
                S[i][j] = fmaf(S[i][j], g[i], k[i] * v[j]);
                acc[j]  = fmaf(q[i], S[i][j], acc[j]);
            }
        }

        // value-folding butterfly: 9 shfl total
        float a4[4];
        #pragma unroll
        for (int j = 0; j < 4; j++) {
            const float send = b4 ? acc[j] : acc[j + 4];
            const float keep = b4 ? acc[j + 4] : acc[j];
            a4[j] = keep + __shfl_xor_sync(0xffffffffu, send, 16);
        }
        float a2[2];
        #pragma unroll
        for (int j = 0; j < 2; j++) {
            const float send = b3 ? a4[j] : a4[j + 2];
            const float keep = b3 ? a4[j + 2] : a4[j];
            a2[j] = keep + __shfl_xor_sync(0xffffffffu, send, 8);
        }
        float s;
        {
            const float send = b2 ? a2[0] : a2[1];
            const float keep = b2 ? a2[1] : a2[0];
            s = keep + __shfl_xor_sync(0xffffffffu, send, 4);
        }
        s += __shfl_xor_sync(0xffffffffu, s, 2);
        s += __shfl_xor_sync(0xffffffffu, s, 1);

        if (writer) yp[(size_t)t * DD + vwi] = s;
    }
}

// -------------------- LayerNorm --------------------
__global__ __launch_bounds__(256)
void ln_kernel(const float* __restrict__ gamma, const float* __restrict__ beta)
{
    const int row = blockIdx.x;
    const float* yr   = g_y + (size_t)row * DD;
    float*       orow = g_q + (size_t)row * DD;
    const int c0 = threadIdx.x * 8;

    const float4 v0 = *(const float4*)(yr + c0);
    const float4 v1 = *(const float4*)(yr + c0 + 4);
    float vals[8] = {v0.x, v0.y, v0.z, v0.w, v1.x, v1.y, v1.z, v1.w};

    float s = 0.f, s2 = 0.f;
    #pragma unroll
    for (int i = 0; i < 8; i++) { s += vals[i]; s2 = fmaf(vals[i], vals[i], s2); }

    #pragma unroll
    for (int m = 16; m >= 1; m >>= 1) {
        s  += __shfl_xor_sync(0xffffffffu, s,  m);
        s2 += __shfl_xor_sync(0xffffffffu, s2, m);
    }
    __shared__ float ws[8], ws2[8];
    const int warp = threadIdx.x >> 5;
    if ((threadIdx.x & 31) == 0) { ws[warp] = s; ws2[warp] = s2; }
    __syncthreads();
    float ts = 0.f, ts2 = 0.f;
    #pragma unroll
    for (int i = 0; i < 8; i++) { ts += ws[i]; ts2 += ws2[i]; }

    const float mu  = ts * (1.0f / DD);
    const float var = ts2 * (1.0f / DD) - mu * mu;
    const float r   = rsqrtf(var + LNEPS);

    const float4 ga0 = *(const float4*)(gamma + c0);
    const float4 ga1 = *(const float4*)(gamma + c0 + 4);
    const float4 be0 = *(const float4*)(beta + c0);
    const float4 be1 = *(const float4*)(beta + c0 + 4);
    float gm[8] = {ga0.x, ga0.y, ga0.z, ga0.w, ga1.x, ga1.y, ga1.z, ga1.w};
    float bt[8] = {be0.x, be0.y, be0.z, be0.w, be1.x, be1.y, be1.z, be1.w};

    float o[8];
    #pragma unroll
    for (int i = 0; i < 8; i++)
        o[i] = tf32_rna(fmaf((vals[i] - mu) * r, gm[i], bt[i]));
    *(float4*)(orow + c0)     = make_float4(o[0], o[1], o[2], o[3]);
    *(float4*)(orow + c0 + 4) = make_float4(o[4], o[5], o[6], o[7]);
}

// -------------------- launch --------------------
extern "C" void kernel_launch(void* const* d_in, const int* in_sizes, int n_in,
                              void* d_out, int out_size)
{
    const float* x     = (const float*)d_in[0];
    const float* Wq    = (const float*)d_in[1];
    const float* Wk    = (const float*)d_in[2];
    const float* Wv    = (const float*)d_in[3];
    const float* Wg    = (const float*)d_in[4];
    const float* Wo    = (const float*)d_in[5];
    const float* gamma = (const float*)d_in[6];
    const float* beta  = (const float*)d_in[7];
    float* out = (float*)d_out;

    cudaFuncSetAttribute(gemm_uni, cudaFuncAttributeMaxDynamicSharedMemorySize, GEMM_SMEM);

    const int nx = MROWS * DD;   // 16M
    const int nw = DD * DD;      // 4M
    tf32_round_kernel<<<nx / (256 * 4), 256>>>(x, 6, nx);
    tf32_round_w_kernel<<<dim3(nw / (256 * 4), 5), 256>>>(Wq, Wk, Wv, Wg, Wo);

    // merged projections: q (QSCALE) | k | v | eg (sigmoid)
    const int actPack = 1 | (0 << 4) | (0 << 8) | (2 << 12);
    gemm_uni<<<dim3(8 * 4, MROWS / TBM), 256, GEMM_SMEM>>>(6, 7, nullptr, 1, actPack);

    // time-split recurrence: local states -> scan -> replay
    gla_p1<<<dim3(2 * NB, HH, BB), 256>>>();
    gla_p2<<<dim3(8, HH, BB), 256>>>(out + (size_t)MROWS * DD);
    gla_p3<<<dim3(2 * NB, HH, BB), 256>>>();

    // layernorm into g_q (tf32-rounded), then output projection into d_out
    ln_kernel<<<MROWS, 256>>>(gamma, beta);
    gemm_uni<<<dim3(8, MROWS / TBM), 256, GEMM_SMEM>>>(1, 11, out, 0, 0);
}

// round 17
// speedup vs baseline: 1.3052x; 1.1089x over previous
#include <cuda_runtime.h>
#include <math.h>
#include <stdint.h>

// Problem constants
#define BB  2
#define LL  4096
#define DD  2048
#define HH  16
#define KK  128
#define VV  128
#define MROWS (BB*LL)          // 8192
#define QSCALE 0.08838834764831845f   // 128^-0.5
#define LNEPS 1e-5f

// recurrence time-split
#define NB  32
#define TB  (LL/NB)            // 128
#define NBH (BB*HH)            // 32

// GEMM tiling (round-13 proven): CTA tile 128x256, BK=32, 2 stages -> 2 CTAs/SM
#define TBM 128
#define TBN 256
#define TBK 32

#define TSTAGES 2
#define A_STAGE_BYTES (TBM*TBK*4)     // 16384
#define B_STAGE_BYTES (TBN*TBK*4)     // 32768
#define STAGE_BYTES   (A_STAGE_BYTES + B_STAGE_BYTES)   // 49152
#define TC_SMEM       (TSTAGES*STAGE_BYTES + 1024)      // 99328

// fallback (correctness-only) smem
#define PADK 36
#define MMA_SMEM ((TBM + TBN) * PADK * 4)               // 55296

#define GEMM_SMEM (TC_SMEM > MMA_SMEM ? TC_SMEM : MMA_SMEM)

// tcgen05 idesc
#define IDESC_TF32 ((1u<<4) | (2u<<7) | (2u<<10) | ((TBN/8)<<17) | ((TBM/16)<<24))
#define DESC_BASE_SW128 ( (2ull<<61) | (1ull<<46) | (64ull<<32) | (1ull<<16) )

#if defined(__CUDA_ARCH_FEAT_SM103_ALL) || defined(__CUDA_ARCH_FEAT_SM100_ALL)
#define TC_PATH 1
#else
#define TC_PATH 0
#endif

// -------------------- scratch --------------------
__device__ float g_q [(size_t)MROWS * DD];
__device__ float g_k [(size_t)MROWS * DD];
__device__ float g_v [(size_t)MROWS * DD];
__device__ float g_eg[(size_t)MROWS * DD];
__device__ float g_y [(size_t)MROWS * DD];
__device__ float g_xt[(size_t)MROWS * DD];
__device__ float g_w [5][(size_t)DD * DD];
__device__ float g_sloc  [(size_t)NB * NBH * KK * VV];
__device__ float g_sstart[(size_t)NB * NBH * KK * VV];
__device__ float g_dec   [(size_t)NB * NBH * KK];

__device__ __forceinline__ float* pick_buf(int sel) {
    switch (sel) {
        case 1: return g_q;
        case 2: return g_k;
        case 3: return g_v;
        case 4: return g_eg;
        case 5: return g_y;
        case 6: return g_xt;
        default: return g_w[sel - 7];
    }
}

// -------------------- tf32 rounding pre-pass --------------------
__device__ __forceinline__ float tf32_rna(float f) {
    uint32_t u;
    asm("cvt.rna.tf32.f32 %0, %1;" : "=r"(u) : "f"(f));
    return __uint_as_float(u);
}

__global__ __launch_bounds__(256)
void tf32_round_kernel(const float* __restrict__ in, int outsel, int n)
{
    float* out = pick_buf(outsel);
    int i = (blockIdx.x * 256 + threadIdx.x) * 4;
    if (i < n) {
        float4 v = *(const float4*)(in + i);
        v.x = tf32_rna(v.x); v.y = tf32_rna(v.y);
        v.z = tf32_rna(v.z); v.w = tf32_rna(v.w);
        *(float4*)(out + i) = v;
    }
}

__global__ __launch_bounds__(256)
void tf32_round_w_kernel(const float* __restrict__ w0, const float* __restrict__ w1,
                         const float* __restrict__ w2, const float* __restrict__ w3,
                         const float* __restrict__ w4)
{
    const float* in;
    switch (blockIdx.y) {
        case 0: in = w0; break;
        case 1: in = w1; break;
        case 2: in = w2; break;
        case 3: in = w3; break;
        default: in = w4; break;
    }
    float* out = g_w[blockIdx.y];
    int i = (blockIdx.x * 256 + threadIdx.x) * 4;
    float4 v = *(const float4*)(in + i);
    v.x = tf32_rna(v.x); v.y = tf32_rna(v.y);
    v.z = tf32_rna(v.z); v.w = tf32_rna(v.w);
    *(float4*)(out + i) = v;
}

// -------------------- common helpers --------------------
__device__ __forceinline__ uint32_t smem_u32(const void* p) {
    return (uint32_t)__cvta_generic_to_shared(p);
}
__device__ __forceinline__ void cp16(uint32_t sa, const float* g) {
    asm volatile("cp.async.cg.shared.global [%0], [%1], 16;\n" :: "r"(sa), "l"(g));
}

#if TC_PATH
__device__ __forceinline__ void mbar_init(uint32_t a, uint32_t cnt) {
    asm volatile("mbarrier.init.shared.b64 [%0], %1;" :: "r"(a), "r"(cnt) : "memory");
}
__device__ __forceinline__ void mbar_wait(uint32_t a, uint32_t parity) {
    asm volatile(
        "{\n\t.reg .pred P;\n\t"
        "WLOOP:\n\t"
        "mbarrier.try_wait.parity.shared.b64 P, [%0], %1;\n\t"
        "@P bra.uni WDONE;\n\t"
        "bra.uni WLOOP;\n\t"
        "WDONE:\n\t}"
        :: "r"(a), "r"(parity) : "memory");
}
__device__ __forceinline__ void mma_tf32_tc(uint32_t d, uint64_t ad, uint64_t bd,
                                            uint32_t idesc, uint32_t en) {
    asm volatile(
        "{\n\t.reg .pred p;\n\t"
        "setp.ne.u32 p, %4, 0;\n\t"
        "tcgen05.mma.cta_group::1.kind::tf32 [%0], %1, %2, %3, {%5,%5,%5,%5}, p;\n\t"
        "}"
        :: "r"(d), "l"(ad), "l"(bd), "r"(idesc), "r"(en), "r"(0u) : "memory");
}
__device__ __forceinline__ void tc_commit(uint32_t mbar) {
    asm volatile(
        "tcgen05.commit.cta_group::1.mbarrier::arrive::one.shared::cluster.b64 [%0];"
        :: "r"(mbar) : "memory");
}
// packed f32x2 helpers (sm_100+)
__device__ __forceinline__ unsigned long long pk2(float a, float b) {
    unsigned long long r;
    asm("mov.b64 %0, {%1, %2};" : "=l"(r) : "f"(a), "f"(b));
    return r;
}
__device__ __forceinline__ unsigned long long mul2(unsigned long long a, unsigned long long b) {
    unsigned long long r;
    asm("mul.rn.f32x2 %0, %1, %2;" : "=l"(r) : "l"(a), "l"(b));
    return r;
}
__device__ __forceinline__ unsigned long long fma2(unsigned long long a, unsigned long long b,
                                                   unsigned long long c) {
    unsigned long long r;
    asm("fma.rn.f32x2 %0, %1, %2, %3;" : "=l"(r) : "l"(a), "l"(b), "l"(c));
    return r;
}
__device__ __forceinline__ void upk2(unsigned long long p, float& lo, float& hi) {
    asm("mov.b64 {%0, %1}, %2;" : "=f"(lo), "=f"(hi) : "l"(p));
}
#else
__device__ __forceinline__ void mma_tf32(float* c, const uint32_t* a, const uint32_t* b)
{
    asm volatile(
        "mma.sync.aligned.m16n8k8.row.col.f32.tf32.tf32.f32 "
        "{%0,%1,%2,%3},{%4,%5,%6,%7},{%8,%9},{%0,%1,%2,%3};\n"
        : "+f"(c[0]), "+f"(c[1]), "+f"(c[2]), "+f"(c[3])
        : "r"(a[0]), "r"(a[1]), "r"(a[2]), "r"(a[3]), "r"(b[0]), "r"(b[1]));
}
#endif

// -------------------- unified GEMM (round-13 proven): C = act(A @ B^T) ----------
__global__ __launch_bounds__(256, 2)
void gemm_uni(int Asel, int Bsel0, float* __restrict__ Cext, int Csel0, int actPack)
{
    extern __shared__ float dsm[];

    const int bnIdx = blockIdx.x & 7;
    const int proj  = blockIdx.x >> 3;

    const float* A = (const float*)pick_buf(Asel);
    const float* B = (const float*)pick_buf(Bsel0 + proj);
    float*       C = Csel0 ? pick_buf(Csel0 + proj) : Cext;
    const int mode = (actPack >> (4 * proj)) & 15;

    const int bm = blockIdx.y * TBM;
    const int bn = bnIdx * TBN;

    const int tid  = threadIdx.x;
    const int warp = tid >> 5, lane = tid & 31;

#if TC_PATH
    __shared__ __align__(8) unsigned long long s_mbar[TSTAGES + 1];
    __shared__ uint32_t s_tmem[1];

    const uint32_t rawb = smem_u32(dsm);
    const uint32_t smb  = (rawb + 1023u) & ~1023u;

    if (warp == 0) {
        asm volatile(
            "tcgen05.alloc.cta_group::1.sync.aligned.shared::cta.b32 [%0], %1;"
            :: "r"(smem_u32(s_tmem)), "r"(256u) : "memory");
        asm volatile("tcgen05.relinquish_alloc_permit.cta_group::1.sync.aligned;");
    }
    if (tid == 0) {
        #pragma unroll
        for (int i = 0; i < TSTAGES + 1; i++)
            mbar_init(smem_u32(&s_mbar[i]), 1u);
    }
    __syncthreads();
    uint32_t tmem_base;
    asm volatile("ld.shared.b32 %0, [%1];" : "=r"(tmem_base) : "r"(smem_u32(s_tmem)));

    const int lr  = tid >> 3;
    const int seg = tid & 7;

    auto loader = [&](int c) {
        const uint32_t sb = smb + (uint32_t)((c & 1) * STAGE_BYTES);
        const float* Ab = A + (size_t)bm * DD + c * TBK;
        #pragma unroll
        for (int i = 0; i < 4; i++) {
            const int row = lr + 32 * i;
            const uint32_t sw = (uint32_t)row * 128u + (uint32_t)((seg ^ (row & 7)) * 16);
            cp16(sb + sw, Ab + (size_t)row * DD + seg * 4);
        }
        const uint32_t bbB = sb + A_STAGE_BYTES;
        const float* Bb = B + (size_t)bn * DD + c * TBK;
        #pragma unroll
        for (int i = 0; i < 8; i++) {
            const int row = lr + 32 * i;
            const uint32_t sw = (uint32_t)row * 128u + (uint32_t)((seg ^ (row & 7)) * 16);
            cp16(bbB + sw, Bb + (size_t)row * DD + seg * 4);
        }
        asm volatile("cp.async.commit_group;\n");
    };

    loader(0); loader(1);

    const int nk = DD / TBK;   // 64
    for (int c = 0; c < nk; c++) {
        asm volatile("cp.async.wait_group 1;\n");
        __syncthreads();

        if (tid == 0) {
            asm volatile("fence.proxy.async.shared::cta;" ::: "memory");
            const uint32_t sb = smb + (uint32_t)((c & 1) * STAGE_BYTES);
            const uint64_t ad = DESC_BASE_SW128 | (uint64_t)((sb >> 4) & 0x3FFF);
            const uint64_t bd = DESC_BASE_SW128 | (uint64_t)(((sb + A_STAGE_BYTES) >> 4) & 0x3FFF);
            #pragma unroll
            for (int k = 0; k < 4; k++)
                mma_tf32_tc(tmem_base, ad + 2 * k, bd + 2 * k, IDESC_TF32,
                            (c > 0 || k > 0) ? 1u : 0u);
            tc_commit(smem_u32(&s_mbar[c & 1]));
        }

        if (c + 2 < nk) {
            mbar_wait(smem_u32(&s_mbar[c & 1]), (uint32_t)((c >> 1) & 1));
            loader(c + 2);
        } else {
            asm volatile("cp.async.commit_group;\n");
        }
    }

    if (tid == 0) tc_commit(smem_u32(&s_mbar[TSTAGES]));
    __syncthreads();
    mbar_wait(smem_u32(&s_mbar[TSTAGES]), 0u);
    asm volatile("tcgen05.fence::after_thread_sync;" ::: "memory");

    const int sub = warp & 3;
    const int cb0 = (warp >> 2) * 128;
    const int row = bm + sub * 32 + lane;
    #pragma unroll
    for (int cb = 0; cb < 128; cb += 32) {
        uint32_t r[32];
        asm volatile(
            "tcgen05.ld.sync.aligned.32x32b.x32.b32 "
            "{%0,%1,%2,%3,%4,%5,%6,%7,%8,%9,%10,%11,%12,%13,%14,%15,"
            "%16,%17,%18,%19,%20,%21,%22,%23,%24,%25,%26,%27,%28,%29,%30,%31}, [%32];"
            : "=r"(r[0]),"=r"(r[1]),"=r"(r[2]),"=r"(r[3]),"=r"(r[4]),"=r"(r[5]),"=r"(r[6]),"=r"(r[7]),
              "=r"(r[8]),"=r"(r[9]),"=r"(r[10]),"=r"(r[11]),"=r"(r[12]),"=r"(r[13]),"=r"(r[14]),"=r"(r[15]),
              "=r"(r[16]),"=r"(r[17]),"=r"(r[18]),"=r"(r[19]),"=r"(r[20]),"=r"(r[21]),"=r"(r[22]),"=r"(r[23]),
              "=r"(r[24]),"=r"(r[25]),"=r"(r[26]),"=r"(r[27]),"=r"(r[28]),"=r"(r[29]),"=r"(r[30]),"=r"(r[31])
            : "r"(tmem_base + cb0 + cb));
        asm volatile("tcgen05.wait::ld.sync.aligned;" ::: "memory");

        float* Crow = C + (size_t)row * DD + bn + cb0 + cb;
        #pragma unroll
        for (int e = 0; e < 32; e += 4) {
            float o[4];
            #pragma unroll
            for (int t = 0; t < 4; t++) {
                float vv = __uint_as_float(r[e + t]);
                if (mode == 1) vv *= QSCALE;
                else if (mode == 2) vv = 1.0f / (1.0f + __expf(-vv));
                o[t] = vv;
            }
            *(float4*)(Crow + e) = make_float4(o[0], o[1], o[2], o[3]);
        }
    }

    __syncthreads();
    if (warp == 0) {
        asm volatile("tcgen05.dealloc.cta_group::1.sync.aligned.b32 %0, %1;"
                     :: "r"(tmem_base), "r"(256u));
    }

#else
    // ====== mma.sync fallback (correctness-only; never runs on sm_103a) ======
    const int wm  = (warp >> 2) * 64;
    const int wn  = (warp & 3) * 64;
    const int grp = lane >> 2, t4 = lane & 3;

    const int lrow = tid >> 3;
    const int lk   = (tid & 7) * 4;

    float acc[4][8][4];
    #pragma unroll
    for (int i = 0; i < 4; i++)
        #pragma unroll
        for (int j = 0; j < 8; j++)
            #pragma unroll
            for (int e = 0; e < 4; e++) acc[i][j][e] = 0.f;

    float* Asm = dsm;
    float* Bsm = dsm + TBM * PADK;

    for (int kt = 0; kt < DD; kt += TBK) {
        __syncthreads();
        #pragma unroll
        for (int i = 0; i < 4; i++) {
            const int row = lrow + 32 * i;
            const float4 av = *(const float4*)(A + (size_t)(bm + row) * DD + kt + lk);
            *(float4*)&Asm[row * PADK + lk] = av;
        }
        #pragma unroll
        for (int i = 0; i < 8; i++) {
            const int row = lrow + 32 * i;
            const float4 bv = *(const float4*)(B + (size_t)(bn + row) * DD + kt + lk);
            *(float4*)&Bsm[row * PADK + lk] = bv;
        }
        __syncthreads();

        #pragma unroll
        for (int k8 = 0; k8 < TBK; k8 += 8) {
            uint32_t a[4][4], b[8][2];
            #pragma unroll
            for (int i = 0; i < 4; i++) {
                const float* ap = Asm + (wm + i * 16 + grp) * PADK + k8 + t4;
                a[i][0] = __float_as_uint(ap[0]);
                a[i][1] = __float_as_uint(ap[8 * PADK]);
                a[i][2] = __float_as_uint(ap[4]);
                a[i][3] = __float_as_uint(ap[8 * PADK + 4]);
            }
            #pragma unroll
            for (int j = 0; j < 8; j++) {
                const float* bp = Bsm + (wn + j * 8 + grp) * PADK + k8 + t4;
                b[j][0] = __float_as_uint(bp[0]);
                b[j][1] = __float_as_uint(bp[4]);
            }
            #pragma unroll
            for (int i = 0; i < 4; i++)
                #pragma unroll
                for (int j = 0; j < 8; j++)
                    mma_tf32(acc[i][j], a[i], b[j]);
        }
    }

    #pragma unroll
    for (int i = 0; i < 4; i++) {
        const int r0 = bm + wm + i * 16 + grp;
        #pragma unroll
        for (int j = 0; j < 8; j++) {
            const int c0 = bn + wn + j * 8 + t4 * 2;
            float o[4];
            #pragma unroll
            for (int e = 0; e < 4; e++) {
                float vv = acc[i][j][e];
                if (mode == 1) vv *= QSCALE;
                else if (mode == 2) vv = 1.0f / (1.0f + __expf(-vv));
                o[e] = vv;
            }
            *(float2*)&C[(size_t)r0 * DD + c0]       = make_float2(o[0], o[1]);
            *(float2*)&C[(size_t)(r0 + 8) * DD + c0] = make_float2(o[2], o[3]);
        }
    }
#endif
}

// ==================== time-split GLA recurrence ====================

// Phase 1 (k-sliced warps; depth-3 prefetch; packed f32x2 math on TC path).
__global__ __launch_bounds__(256, 2)
void gla_p1()
{
    const int lane = threadIdx.x & 31;
    const int w    = threadIdx.x >> 5;
    const int kl   = lane & 3;
    const int vl   = lane >> 2;
    const int vc   = blockIdx.x & 1;
    const int blk  = blockIdx.x >> 1;
    const int h    = blockIdx.y;
    const int b    = blockIdx.z;
    const int kofs = w * 16 + kl * 4;
    const int vabs = vc * 64 + vl * 8;

    const size_t base = ((size_t)b * LL + (size_t)blk * TB) * DD + (size_t)h * KK;
    const float* kp = g_k  + base + kofs;
    const float* gp = g_eg + base + kofs;
    const float* vp = g_v  + base + vabs;

    const size_t bh = (size_t)b * HH + h;
    const size_t so = (((size_t)blk * NBH + bh) * KK + kofs) * VV + vabs;
    const size_t dofs = ((size_t)blk * NBH + bh) * KK + kofs;

#if TC_PATH
    unsigned long long S2[4][4];
    float dp[4];
    #pragma unroll
    for (int i = 0; i < 4; i++) {
        dp[i] = 1.f;
        #pragma unroll
        for (int j = 0; j < 4; j++) S2[i][j] = 0ull;
    }

    struct F { float4 k, g; ulonglong2 va, vb; } f[4];
    auto ld = [&](F& fr, int t) {
        const size_t off = (size_t)t * DD;
        fr.k  = *(const float4*)(kp + off);
        fr.g  = *(const float4*)(gp + off);
        fr.va = *(const ulonglong2*)(vp + off);
        fr.vb = *(const ulonglong2*)(vp + off + 4);
    };
    ld(f[0], 0); ld(f[1], 1); ld(f[2], 2);

    #pragma unroll 4
    for (int t = 0; t < TB; ++t) {
        const int tn = (t + 3 < TB) ? (t + 3) : (TB - 1);
        ld(f[(t + 3) & 3], tn);

        const F& c = f[t & 3];
        float k[4] = {c.k.x, c.k.y, c.k.z, c.k.w};
        float g[4] = {c.g.x, c.g.y, c.g.z, c.g.w};
        unsigned long long v2[4] = {c.va.x, c.va.y, c.vb.x, c.vb.y};

        #pragma unroll
        for (int i = 0; i < 4; i++) {
            dp[i] *= g[i];
            const unsigned long long k2 = pk2(k[i], k[i]);
            const unsigned long long g2 = pk2(g[i], g[i]);
            #pragma unroll
            for (int j = 0; j < 4; j++)
                S2[i][j] = fma2(S2[i][j], g2, mul2(k2, v2[j]));
        }
    }

    #pragma unroll
    for (int i = 0; i < 4; i++) {
        ulonglong2 o0; o0.x = S2[i][0]; o0.y = S2[i][1];
        ulonglong2 o1; o1.x = S2[i][2]; o1.y = S2[i][3];
        *(ulonglong2*)&g_sloc[so + (size_t)i * VV]     = o0;
        *(ulonglong2*)&g_sloc[so + (size_t)i * VV + 4] = o1;
    }
    if (vl == 0 && vc == 0) {
        #pragma unroll
        for (int i = 0; i < 4; i++) g_dec[dofs + i] = dp[i];
    }
#else
    float S[4][8];
    float dp[4];
    #pragma unroll
    for (int i = 0; i < 4; i++) {
        dp[i] = 1.f;
        #pragma unroll
        for (int j = 0; j < 8; j++) S[i][j] = 0.f;
    }

    struct F { float4 k, g, v0, v1; } f[4];
    auto ld = [&](F& fr, int t) {
        const size_t off = (size_t)t * DD;
        fr.k  = *(const float4*)(kp + off);
        fr.g  = *(const float4*)(gp + off);
        fr.v0 = *(const float4*)(vp + off);
        fr.v1 = *(const float4*)(vp + off + 4);
    };
    ld(f[0], 0); ld(f[1], 1); ld(f[2], 2);

    #pragma unroll 4
    for (int t = 0; t < TB; ++t) {
        const int tn = (t + 3 < TB) ? (t + 3) : (TB - 1);
        ld(f[(t + 3) & 3], tn);

        const F& c = f[t & 3];
        float k[4] = {c.k.x, c.k.y, c.k.z, c.k.w};
        float g[4] = {c.g.x, c.g.y, c.g.z, c.g.w};
        float v[8] = {c.v0.x, c.v0.y, c.v0.z, c.v0.w, c.v1.x, c.v1.y, c.v1.z, c.v1.w};

        #pragma unroll
        for (int i = 0; i < 4; i++) {
            dp[i] *= g[i];
            #pragma unroll
            for (int j = 0; j < 8; j++)
                S[i][j] = fmaf(S[i][j], g[i], k[i] * v[j]);
        }
    }

    #pragma unroll
    for (int i = 0; i < 4; i++) {
        *(float4*)&g_sloc[so + (size_t)i * VV]     = make_float4(S[i][0], S[i][1], S[i][2], S[i][3]);
        *(float4*)&g_sloc[so + (size_t)i * VV + 4] = make_float4(S[i][4], S[i][5], S[i][6], S[i][7]);
    }
    if (vl == 0 && vc == 0) {
        #pragma unroll
        for (int i = 0; i < 4; i++) g_dec[dofs + i] = dp[i];
    }
#endif
}

// Phase 2: k split over CTAs (x4): grid (16, H, B).
// blockIdx.x = (kqh << 2) | vchunk; 256 thr = 8 kq-groups(4k) x 32 vslots(1v).
__global__ __launch_bounds__(256)
void gla_p2(float* __restrict__ out_state)
{
    const int tid   = threadIdx.x;
    const int vslot = tid & 31;
    const int kq    = tid >> 5;          // 0..7
    const int vchunk = blockIdx.x & 3;
    const int kqh    = blockIdx.x >> 2;  // 0..3
    const int kofs  = kqh * 32 + kq * 4;
    const int vabs  = vchunk * 32 + vslot;
    const int h     = blockIdx.y;
    const int b     = blockIdx.z;
    const size_t bh = (size_t)b * HH + h;

    float R[4];
    #pragma unroll
    for (int i = 0; i < 4; i++) R[i] = 0.f;

    for (int i = 0; i < NB; i++) {
        const size_t so   = (((size_t)i * NBH + bh) * KK + kofs) * VV + vabs;
        const size_t dofs = ((size_t)i * NBH + bh) * KK + kofs;
        #pragma unroll
        for (int j = 0; j < 4; j++) {
            g_sstart[so + (size_t)j * VV] = R[j];
            const float sl = g_sloc[so + (size_t)j * VV];
            const float d  = g_dec[dofs + j];
            R[j] = fmaf(d, R[j], sl);
        }
    }

    const size_t fsbase = (bh * KK + kofs) * VV + vabs;
    #pragma unroll
    for (int j = 0; j < 4; j++)
        out_state[fsbase + (size_t)j * VV] = R[j];
}

// Phase 3 (Layout D + value-folding reduction; packed f32x2 math on TC path).
__global__ __launch_bounds__(256, 2)
void gla_p3()
{
    const int lane = threadIdx.x & 31;
    const int w    = threadIdx.x >> 5;
    const int vc   = blockIdx.x & 1;
    const int blk  = blockIdx.x >> 1;
    const int vabs = vc * 64 + w * 8;
    const int h    = blockIdx.y;
    const int b    = blockIdx.z;

    const size_t base = ((size_t)b * LL + (size_t)blk * TB) * DD + (size_t)h * KK;
    const float* qp = g_q  + base + lane * 4;
    const float* kp = g_k  + base + lane * 4;
    const float* gp = g_eg + base + lane * 4;
    const float* vp = g_v  + base + vabs;
    float*       yp = g_y  + base + vabs;

    const size_t bh = (size_t)b * HH + h;
    const size_t so = (((size_t)blk * NBH + bh) * KK + lane * 4) * VV + vabs;

    // fold helpers
    const bool b4 = (lane & 16) != 0;
    const bool b3 = (lane & 8)  != 0;
    const bool b2 = (lane & 4)  != 0;
    const int  vwi = ((lane >> 4) & 1) * 4 + ((lane >> 3) & 1) * 2 + ((lane >> 2) & 1);
    const bool writer = (lane & 3) == 0;

#if TC_PATH
    unsigned long long S2[4][4];
    #pragma unroll
    for (int i = 0; i < 4; i++) {
        const ulonglong2 s0 = *(const ulonglong2*)&g_sstart[so + (size_t)i * VV];
        const ulonglong2 s1 = *(const ulonglong2*)&g_sstart[so + (size_t)i * VV + 4];
        S2[i][0] = s0.x; S2[i][1] = s0.y; S2[i][2] = s1.x; S2[i][3] = s1.y;
    }

    struct F { float4 q, k, g; ulonglong2 va, vb; } f[3];
    auto ld = [&](F& fr, int t) {
        const size_t off = (size_t)t * DD;
        fr.q  = *(const float4*)(qp + off);
        fr.k  = *(const float4*)(kp + off);
        fr.g  = *(const float4*)(gp + off);
        fr.va = *(const ulonglong2*)(vp + off);
        fr.vb = *(const ulonglong2*)(vp + off + 4);
    };
    ld(f[0], 0); ld(f[1], 1);

    #pragma unroll 3
    for (int t = 0; t < TB; ++t) {
        const int tn = (t + 2 < TB) ? (t + 2) : (TB - 1);
        ld(f[(t + 2) % 3], tn);

        const F& c = f[t % 3];
        float q[4] = {c.q.x, c.q.y, c.q.z, c.q.w};
        float k[4] = {c.k.x, c.k.y, c.k.z, c.k.w};
        float g[4] = {c.g.x, c.g.y, c.g.z, c.g.w};
        unsigned long long v2[4] = {c.va.x, c.va.y, c.vb.x, c.vb.y};

        unsigned long long acc2[4] = {0ull, 0ull, 0ull, 0ull};
        #pragma unroll
        for (int i = 0; i < 4; i++) {
            const unsigned long long q2 = pk2(q[i], q[i]);
            const unsigned long long k2 = pk2(k[i], k[i]);
            const unsigned long long g2 = pk2(g[i], g[i]);
            #pragma unroll
            for (int j = 0; j < 4; j++) {
                S2[i][j] = fma2(S2[i][j], g2, mul2(k2, v2[j]));
                acc2[j]  = fma2(q2, S2[i][j], acc2[j]);
            }
        }

        float acc[8];
        #pragma unroll
        for (int j = 0; j < 4; j++) upk2(acc2[j], acc[2 * j], acc[2 * j + 1]);

        // value-folding butterfly: 9 shfl total
        float a4[4];
        #pragma unroll
        for (int j = 0; j < 4; j++) {
            const float send = b4 ? acc[j] : acc[j + 4];
            const float keep = b4 ? acc[j + 4] : acc[j];
            a4[j] = keep + __shfl_xor_sync(0xffffffffu, send, 16);
        }
        float a2[2];
        #pragma unroll
        for (int j = 0; j < 2; j++) {
            const float send = b3 ? a4[j] : a4[j + 2];
            const float keep = b3 ? a4[j + 2] : a4[j];
            a2[j] = keep + __shfl_xor_sync(0xffffffffu, send, 8);
        }
        float s;
        {
            const float send = b2 ? a2[0] : a2[1];
            const float keep = b2 ? a2[1] : a2[0];
            s = keep + __shfl_xor_sync(0xffffffffu, send, 4);
        }
        s += __shfl_xor_sync(0xffffffffu, s, 2);
        s += __shfl_xor_sync(0xffffffffu, s, 1);

        if (writer) yp[(size_t)t * DD + vwi] = s;
    }
#else
    float S[4][8];
    #pragma unroll
    for (int i = 0; i < 4; i++) {
        const float4 s0 = *(const float4*)&g_sstart[so + (size_t)i * VV];
        const float4 s1 = *(const float4*)&g_sstart[so + (size_t)i * VV + 4];
        S[i][0] = s0.x; S[i][1] = s0.y; S[i][2] = s0.z; S[i][3] = s0.w;
        S[i][4] = s1.x; S[i][5] = s1.y; S[i][6] = s1.z; S[i][7] = s1.w;
    }

    struct F { float4 q, k, g, v0, v1; } f[3];
    auto ld = [&](F& fr, int t) {
        const size_t off = (size_t)t * DD;
        fr.q  = *(const float4*)(qp + off);
        fr.k  = *(const float4*)(kp + off);
        fr.g  = *(const float4*)(gp + off);
        fr.v0 = *(const float4*)(vp + off);
        fr.v1 = *(const float4*)(vp + off + 4);
    };
    ld(f[0], 0); ld(f[1], 1);

    #pragma unroll 3
    for (int t = 0; t < TB; ++t) {
        const int tn = (t + 2 < TB) ? (t + 2) : (TB - 1);
        ld(f[(t + 2) % 3], tn);

        const F& c = f[t % 3];
        float q[4] = {c.q.x, c.q.y, c.q.z, c.q.w};
        float k[4] = {c.k.x, c.k.y, c.k.z, c.k.w};
        float g[4] = {c.g.x, c.g.y, c.g.z, c.g.w};
        float v[8] = {c.v0.x, c.v0.y, c.v0.z, c.v0.w, c.v1.x, c.v1.y, c.v1.z, c.v1.w};

        float acc[8] = {0.f,0.f,0.f,0.f,0.f,0.f,0.f,0.f};
        #pragma unroll
        for (int i = 0; i < 4; i++) {
            #pragma unroll
            for (int j = 0; j < 8; j++) {
                S[i][j] = fmaf(S[i][j], g[i], k[i] * v[j]);
                acc[j]  = fmaf(q[i], S[i][j], acc[j]);
            }
        }

        float a4[4];
        #pragma unroll
        for (int j = 0; j < 4; j++) {
            const float send = b4 ? acc[j] : acc[j + 4];
            const float keep = b4 ? acc[j + 4] : acc[j];
            a4[j] = keep + __shfl_xor_sync(0xffffffffu, send, 16);
        }
        float a2[2];
        #pragma unroll
        for (int j = 0; j < 2; j++) {
            const float send = b3 ? a4[j] : a4[j + 2];
            const float keep = b3 ? a4[j + 2] : a4[j];
            a2[j] = keep + __shfl_xor_sync(0xffffffffu, send, 8);
        }
        float s;
        {
            const float send = b2 ? a2[0] : a2[1];
            const float keep = b2 ? a2[1] : a2[0];
            s = keep + __shfl_xor_sync(0xffffffffu, send, 4);
        }
        s += __shfl_xor_sync(0xffffffffu, s, 2);
        s += __shfl_xor_sync(0xffffffffu, s, 1);

        if (writer) yp[(size_t)t * DD + vwi] = s;
    }
#endif
}

// -------------------- LayerNorm --------------------
__global__ __launch_bounds__(256)
void ln_kernel(const float* __restrict__ gamma, const float* __restrict__ beta)
{
    const int row = blockIdx.x;
    const float* yr   = g_y + (size_t)row * DD;
    float*       orow = g_q + (size_t)row * DD;
    const int c0 = threadIdx.x * 8;

    const float4 v0 = *(const float4*)(yr + c0);
    const float4 v1 = *(const float4*)(yr + c0 + 4);
    float vals[8] = {v0.x, v0.y, v0.z, v0.w, v1.x, v1.y, v1.z, v1.w};

    float s = 0.f, s2 = 0.f;
    #pragma unroll
    for (int i = 0; i < 8; i++) { s += vals[i]; s2 = fmaf(vals[i], vals[i], s2); }

    #pragma unroll
    for (int m = 16; m >= 1; m >>= 1) {
        s  += __shfl_xor_sync(0xffffffffu, s,  m);
        s2 += __shfl_xor_sync(0xffffffffu, s2, m);
    }
    __shared__ float ws[8], ws2[8];
    const int warp = threadIdx.x >> 5;
    if ((threadIdx.x & 31) == 0) { ws[warp] = s; ws2[warp] = s2; }
    __syncthreads();
    float ts = 0.f, ts2 = 0.f;
    #pragma unroll
    for (int i = 0; i < 8; i++) { ts += ws[i]; ts2 += ws2[i]; }

    const float mu  = ts * (1.0f / DD);
    const float var = ts2 * (1.0f / DD) - mu * mu;
    const float r   = rsqrtf(var + LNEPS);

    const float4 ga0 = *(const float4*)(gamma + c0);
    const float4 ga1 = *(const float4*)(gamma + c0 + 4);
    const float4 be0 = *(const float4*)(beta + c0);
    const float4 be1 = *(const float4*)(beta + c0 + 4);
    float gm[8] = {ga0.x, ga0.y, ga0.z, ga0.w, ga1.x, ga1.y, ga1.z, ga1.w};
    float bt[8] = {be0.x, be0.y, be0.z, be0.w, be1.x, be1.y, be1.z, be1.w};

    float o[8];
    #pragma unroll
    for (int i = 0; i < 8; i++)
        o[i] = tf32_rna(fmaf((vals[i] - mu) * r, gm[i], bt[i]));
    *(float4*)(orow + c0)     = make_float4(o[0], o[1], o[2], o[3]);
    *(float4*)(orow + c0 + 4) = make_float4(o[4], o[5], o[6], o[7]);
}

// -------------------- launch --------------------
extern "C" void kernel_launch(void* const* d_in, const int* in_sizes, int n_in,
                              void* d_out, int out_size)
{
    const float* x     = (const float*)d_in[0];
    const float* Wq    = (const float*)d_in[1];
    const float* Wk    = (const float*)d_in[2];
    const float* Wv    = (const float*)d_in[3];
    const float* Wg    = (const float*)d_in[4];
    const float* Wo    = (const float*)d_in[5];
    const float* gamma = (const float*)d_in[6];
    const float* beta  = (const float*)d_in[7];
    float* out = (float*)d_out;

    cudaFuncSetAttribute(gemm_uni, cudaFuncAttributeMaxDynamicSharedMemorySize, GEMM_SMEM);

    const int nx = MROWS * DD;   // 16M
    const int nw = DD * DD;      // 4M
    tf32_round_kernel<<<nx / (256 * 4), 256>>>(x, 6, nx);
    tf32_round_w_kernel<<<dim3(nw / (256 * 4), 5), 256>>>(Wq, Wk, Wv, Wg, Wo);

    // merged projections: q (QSCALE) | k | v | eg (sigmoid)
    const int actPack = 1 | (0 << 4) | (0 << 8) | (2 << 12);
    gemm_uni<<<dim3(8 * 4, MROWS / TBM), 256, GEMM_SMEM>>>(6, 7, nullptr, 1, actPack);

    // time-split recurrence: local states -> scan -> replay
    gla_p1<<<dim3(2 * NB, HH, BB), 256>>>();
    gla_p2<<<dim3(16, HH, BB), 256>>>(out + (size_t)MROWS * DD);
    gla_p3<<<dim3(2 * NB, HH, BB), 256>>>();

    // layernorm into g_q (tf32-rounded), then output projection into d_out
    ln_kernel<<<MROWS, 256>>>(gamma, beta);
    gemm_uni<<<dim3(8, MROWS / TBM), 256, GEMM_SMEM>>>(1, 11, out, 0, 0);
}